// round 12
// baseline (speedup 1.0000x reference)
#include <cuda_runtime.h>
#include <cuda_fp16.h>
#include <cstdint>
#include <math.h>

#define BATCH 8192
#define RROLE 6
#define DDIM 1024
#define HDIM 256
#define MROWS (BATCH * RROLE)          // 49152
#define M2 (2 * MROWS)                 // 98304 (src+tgt merged)
#define TEMP_INV 2.0f
#define SINKHORN_ITERS 5

#define OUT_ANSWER_OFF  0
#define OUT_MAPPING_OFF ((size_t)MROWS * DDIM)
#define OUT_MAPPED_OFF  (OUT_MAPPING_OFF + (size_t)BATCH * RROLE * RROLE)
#define OUT_CONF_OFF    (OUT_MAPPED_OFF + (size_t)MROWS * HDIM)

#define WSCALE 1024.0f
#define ISCALE (1.0f / 1024.0f)

// plane strides (elements per plane)
#define PX1  ((size_t)M2 * 256)
#define PH   ((size_t)M2 * 512)
#define PE   ((size_t)M2 * 256)

// ---------------- device scratch ----------------
__device__ float g_Wf[HDIM * 2 * HDIM];
__device__ float g_enc[(size_t)M2 * 256];          // rows 0..M-1 src, M..2M-1 tgt
__device__ float g_u[(size_t)MROWS * 256];
__device__ float g_s[(size_t)M2];                  // rmsnorm row scales

__device__ __half g_x1P  [2 * (size_t)M2 * 256];   // unnormalized layer1 out planes
__device__ __half g_hP   [2 * (size_t)M2 * 512];
__device__ __half g_encP [2 * (size_t)M2 * 256];
__device__ __half g_combP[(size_t)MROWS * 512];    // hi plane only (answer path)
__device__ __half g_bigP [(size_t)MROWS * 512];    // hi plane only

// fp16 weight planes (2 planes each, scaled by WSCALE)
__device__ __half g_W1P [2 * 256 * 1024];
__device__ __half g_WabP[2 * 1024 * 256];   // interleaved gate/value rows, g1-folded
__device__ __half g_WfP [2 * 256 * 512];
__device__ __half g_WbTP[2 * 256 * 256];
__device__ __half g_Wa1P[2 * 512 * 512];
__device__ __half g_Wa2P[2 * 1024 * 512];

// ---------------- helpers ----------------
__device__ __forceinline__ uint32_t smem_u32(const void* p) {
    uint32_t a;
    asm("{ .reg .u64 t; cvta.to.shared.u64 t, %1; cvt.u32.u64 %0, t; }" : "=r"(a) : "l"(p));
    return a;
}
__device__ __forceinline__ float gelu_tanh(float x) {
    float x3 = x * x * x;
    return 0.5f * x * (1.0f + tanhf(0.7978845608028654f * (x + 0.044715f * x3)));
}
__device__ __forceinline__ void ldsm4(uint32_t& r0, uint32_t& r1, uint32_t& r2, uint32_t& r3,
                                      uint32_t addr) {
    asm volatile("ldmatrix.sync.aligned.m8n8.x4.shared.b16 {%0,%1,%2,%3}, [%4];"
                 : "=r"(r0), "=r"(r1), "=r"(r2), "=r"(r3) : "r"(addr));
}
__device__ __forceinline__ void mma16816(float* c, const uint32_t* a, const uint32_t* b) {
    asm volatile("mma.sync.aligned.m16n8k16.row.col.f32.f16.f16.f32 "
                 "{%0,%1,%2,%3}, {%4,%5,%6,%7}, {%8,%9}, {%0,%1,%2,%3};"
                 : "+f"(c[0]), "+f"(c[1]), "+f"(c[2]), "+f"(c[3])
                 : "r"(a[0]), "r"(a[1]), "r"(a[2]), "r"(a[3]), "r"(b[0]), "r"(b[1]));
}
__device__ __forceinline__ uint32_t packh(float x, float y) {
    __half h0 = __float2half(x), h1 = __float2half(y);
    return (uint32_t)__half_as_ushort(h0) | ((uint32_t)__half_as_ushort(h1) << 16);
}
#define CP_ASYNC16(dst, src) \
    asm volatile("cp.async.cg.shared.global [%0], [%1], 16;" :: "r"(dst), "l"(src) : "memory")
#define CP_COMMIT() asm volatile("cp.async.commit_group;" ::: "memory")
#define CP_WAIT0()  asm volatile("cp.async.wait_group 0;" ::: "memory")
#define CP_WAIT1()  asm volatile("cp.async.wait_group 1;" ::: "memory")
#define CP_WAIT2()  asm volatile("cp.async.wait_group 2;" ::: "memory")

// ---------------- layer1 GEMM: fp32 A, in-kernel split, 2-stage ----------------
// Writes UNNORMALIZED fp16 planes (hi @0, lo @PX1) of x1 = A@W1^T + b1.
#define GBUF 30720
#define SMEM_L1 61440

__global__ __launch_bounds__(256, 2) void gemm_l1(
    const float* __restrict__ Asrc, const float* __restrict__ Atgt,
    const __half* __restrict__ Bp, size_t bPstride,
    const float* __restrict__ bias, __half* __restrict__ Cp,
    int N, int K, int Nout)
{
    extern __shared__ char smem[];
    const uint32_t sb = smem_u32(smem);
    const int tid = threadIdx.x, lane = tid & 31, wid = tid >> 5;
    const int bm = blockIdx.y * 128, bn = blockIdx.x * 64;
    const int wm = (wid >> 1) * 32, wn = (wid & 1) * 32;

    const float* A = (bm < MROWS) ? Asrc : (Atgt - (size_t)MROWS * K);

    const uint32_t aLd0 = sb + (uint32_t)((wm + (lane & 15)) * 80 + (lane >> 4) * 16);
    const uint32_t bLd0 = sb + 20480u +
        (uint32_t)(((wn + (lane & 7) + ((lane >> 4) & 1) * 8) * 80) + ((lane >> 3) & 1) * 16);

    float acc[2][4][4];
#pragma unroll
    for (int mt = 0; mt < 2; mt++)
#pragma unroll
        for (int nt = 0; nt < 4; nt++)
#pragma unroll
            for (int i = 0; i < 4; i++) acc[mt][nt][i] = 0.0f;

    const int nkb = K >> 5;

    const int arow = tid >> 1, acol = (tid & 1) * 16;
    const float* aBase = A + (size_t)(bm + arow) * K + acol;
    const uint32_t aStsOff = (uint32_t)(arow * 80 + acol * 2);
    const int brow = tid >> 2, bseg = tid & 3;
    const __half* bBase = Bp + (size_t)(bn + brow) * K + bseg * 8;
    const uint32_t bSts = sb + 20480u + (uint32_t)(brow * 80 + bseg * 16);

    {
        float v[16];
#pragma unroll
        for (int j = 0; j < 4; j++)
            *(float4*)(v + j * 4) = *(const float4*)(aBase + j * 4);
        uint32_t hp[8], lp[8];
#pragma unroll
        for (int j = 0; j < 8; j++) {
            __half h0 = __float2half(v[2 * j]), h1 = __float2half(v[2 * j + 1]);
            hp[j] = (uint32_t)__half_as_ushort(h0) | ((uint32_t)__half_as_ushort(h1) << 16);
            lp[j] = packh(v[2 * j] - __half2float(h0), v[2 * j + 1] - __half2float(h1));
        }
        *(uint4*)(smem + aStsOff)              = *(uint4*)hp;
        *(uint4*)(smem + aStsOff + 16)         = *(uint4*)(hp + 4);
        *(uint4*)(smem + aStsOff + 10240)      = *(uint4*)lp;
        *(uint4*)(smem + aStsOff + 10240 + 16) = *(uint4*)(lp + 4);
#pragma unroll
        for (int pl = 0; pl < 2; pl++)
            CP_ASYNC16(bSts + pl * 5120u, bBase + (size_t)pl * bPstride);
        CP_COMMIT();
        CP_WAIT0();
        __syncthreads();
    }

    for (int kb = 0; kb < nkb; kb++) {
        const uint32_t cur = (uint32_t)(kb & 1) * GBUF;
        const uint32_t nxt = (uint32_t)((kb + 1) & 1) * GBUF;
        const bool has = (kb + 1) < nkb;

        float vstage[16];
        if (has) {
            const float* ap = aBase + (kb + 1) * 32;
#pragma unroll
            for (int j = 0; j < 4; j++)
                *(float4*)(vstage + j * 4) = *(const float4*)(ap + j * 4);
            const __half* bp = bBase + (kb + 1) * 32;
#pragma unroll
            for (int pl = 0; pl < 2; pl++)
                CP_ASYNC16(bSts + nxt + pl * 5120u, bp + (size_t)pl * bPstride);
        }
        CP_COMMIT();

#pragma unroll
        for (int ks = 0; ks < 2; ks++) {
            uint32_t af[2][2][4];
#pragma unroll
            for (int mt = 0; mt < 2; mt++)
#pragma unroll
                for (int pl = 0; pl < 2; pl++)
                    ldsm4(af[mt][pl][0], af[mt][pl][1], af[mt][pl][2], af[mt][pl][3],
                          aLd0 + cur + pl * 10240u + mt * 16 * 80 + ks * 32);
            uint32_t bf[2][4][2];
#pragma unroll
            for (int pl = 0; pl < 2; pl++)
#pragma unroll
                for (int nt2 = 0; nt2 < 2; nt2++) {
                    uint32_t r0, r1, r2, r3;
                    ldsm4(r0, r1, r2, r3,
                          bLd0 + cur + pl * 5120u + nt2 * 16 * 80 + ks * 32);
                    bf[pl][nt2 * 2][0] = r0; bf[pl][nt2 * 2][1] = r1;
                    bf[pl][nt2 * 2 + 1][0] = r2; bf[pl][nt2 * 2 + 1][1] = r3;
                }
#pragma unroll
            for (int prod = 0; prod < 3; prod++) {
                const int apl = (prod == 2) ? 1 : 0;
                const int bpl = (prod == 1) ? 1 : 0;
#pragma unroll
                for (int mt = 0; mt < 2; mt++)
#pragma unroll
                    for (int nt = 0; nt < 4; nt++)
                        mma16816(acc[mt][nt], af[mt][apl], bf[bpl][nt]);
            }
        }

        if (has) {
            uint32_t hp[8], lp[8];
#pragma unroll
            for (int j = 0; j < 8; j++) {
                __half h0 = __float2half(vstage[2 * j]), h1 = __float2half(vstage[2 * j + 1]);
                hp[j] = (uint32_t)__half_as_ushort(h0) | ((uint32_t)__half_as_ushort(h1) << 16);
                lp[j] = packh(vstage[2 * j] - __half2float(h0), vstage[2 * j + 1] - __half2float(h1));
            }
            uint32_t off = aStsOff + nxt;
            *(uint4*)(smem + off)              = *(uint4*)hp;
            *(uint4*)(smem + off + 16)         = *(uint4*)(hp + 4);
            *(uint4*)(smem + off + 10240)      = *(uint4*)lp;
            *(uint4*)(smem + off + 10240 + 16) = *(uint4*)(lp + 4);
        }
        CP_WAIT0();
        __syncthreads();
    }

    // epilogue: bias, write fp16 hi/lo planes
#pragma unroll
    for (int mt = 0; mt < 2; mt++) {
        int row0 = bm + wm + mt * 16 + (lane >> 2);
#pragma unroll
        for (int nt = 0; nt < 4; nt++) {
            int col0 = bn + wn + nt * 8 + (lane & 3) * 2;
            float b0 = bias[col0], b1 = bias[col0 + 1];
            float o0 = acc[mt][nt][0] * ISCALE + b0;
            float o1 = acc[mt][nt][1] * ISCALE + b1;
            float o2 = acc[mt][nt][2] * ISCALE + b0;
            float o3 = acc[mt][nt][3] * ISCALE + b1;
            __half h0 = __float2half(o0), h1 = __float2half(o1);
            __half h2 = __float2half(o2), h3 = __float2half(o3);
            *(uint32_t*)(Cp + (size_t)row0 * Nout + col0) =
                (uint32_t)__half_as_ushort(h0) | ((uint32_t)__half_as_ushort(h1) << 16);
            *(uint32_t*)(Cp + PX1 + (size_t)row0 * Nout + col0) =
                packh(o0 - __half2float(h0), o1 - __half2float(h1));
            *(uint32_t*)(Cp + (size_t)(row0 + 8) * Nout + col0) =
                (uint32_t)__half_as_ushort(h2) | ((uint32_t)__half_as_ushort(h3) << 16);
            *(uint32_t*)(Cp + PX1 + (size_t)(row0 + 8) * Nout + col0) =
                packh(o2 - __half2float(h2), o3 - __half2float(h3));
        }
    }
}

// ---------------- HMMA GEMM (multi-stage pipelined, fp16-plane A) ----------------
// NPROD=3: A 2 planes, B 2 planes, hh+hl+lh (3 stages).
// NPROD=1: A hi, B hi, hh only (4 stages).
// ACT: 0 none, 1 gelu, 2 swiglu (rowS scale applied pre-activation).
// OUTMODE bit0 fp32, bit1 fp16 hi+lo, bit2 fp16 hi, bit3: planes only rows<MROWS.
template <int ACT, int OUTMODE, int NPROD>
__global__ __launch_bounds__(256, 2) void gemm_mma(
    const __half* __restrict__ Ap, size_t aPstride,
    const __half* __restrict__ Bp, size_t bPstride,
    const float* __restrict__ bias,
    const float* __restrict__ rowS,
    float* __restrict__ Cf,
    __half* __restrict__ Cp, size_t cPstride,
    int N, int K, int Nout)
{
    constexpr int A_PL = (NPROD == 3) ? 2 : 1;
    constexpr int B_PL = (NPROD >= 2) ? 2 : 1;
    constexpr uint32_t ASZ = A_PL * 10240u;
    constexpr uint32_t STG_SZ = ASZ + B_PL * 5120u;
    constexpr int NSTG = (NPROD == 1) ? 4 : 3;

    extern __shared__ char smem[];
    const uint32_t sb = smem_u32(smem);
    const int tid = threadIdx.x, lane = tid & 31, wid = tid >> 5;
    const int bm = blockIdx.y * 128, bn = blockIdx.x * 64;
    const int wm = (wid >> 1) * 32, wn = (wid & 1) * 32;

    const uint32_t aLd0 = sb + (uint32_t)((wm + (lane & 15)) * 80 + (lane >> 4) * 16);
    const uint32_t bLd0 = sb + ASZ +
        (uint32_t)(((wn + (lane & 7) + ((lane >> 4) & 1) * 8) * 80) + ((lane >> 3) & 1) * 16);

    float acc[2][4][4];
#pragma unroll
    for (int mt = 0; mt < 2; mt++)
#pragma unroll
        for (int nt = 0; nt < 4; nt++)
#pragma unroll
            for (int i = 0; i < 4; i++) acc[mt][nt][i] = 0.0f;

    const int nkb = K >> 5;

    auto issue = [&](int kidx, uint32_t base) {
#pragma unroll
        for (int t = 0; t < 2 * A_PL; t++) {
            int idx = t * 256 + tid;
            int pl = idx >> 9, row = (idx >> 2) & 127, s = idx & 3;
            const __half* srcp = Ap + (size_t)pl * aPstride + (size_t)(bm + row) * K
                                 + kidx * 32 + s * 8;
            CP_ASYNC16(base + pl * 10240u + row * 80u + s * 16u, srcp);
        }
#pragma unroll
        for (int t = 0; t < B_PL; t++) {
            int idx = t * 256 + tid;
            int pl = idx >> 8, row = (idx >> 2) & 63, s = idx & 3;
            const __half* srcp = Bp + (size_t)pl * bPstride + (size_t)(bn + row) * K
                                 + kidx * 32 + s * 8;
            CP_ASYNC16(base + ASZ + pl * 5120u + row * 80u + s * 16u, srcp);
        }
    };

    issue(0, sb);
    CP_COMMIT();
#pragma unroll
    for (int s = 1; s < NSTG - 1; s++) {
        if (nkb > s) issue(s, sb + s * STG_SZ);
        CP_COMMIT();
    }

    uint32_t curStage = 0;
    for (int kb = 0; kb < nkb; kb++) {
        if (NSTG == 3) CP_WAIT1(); else CP_WAIT2();
        __syncthreads();
        const uint32_t cur = curStage * STG_SZ;
        uint32_t nxtStage = curStage + (NSTG - 1);
        if (nxtStage >= NSTG) nxtStage -= NSTG;
        if (kb + NSTG - 1 < nkb) issue(kb + NSTG - 1, sb + nxtStage * STG_SZ);
        CP_COMMIT();
        curStage = (curStage + 1 == NSTG) ? 0 : curStage + 1;

#pragma unroll
        for (int ks = 0; ks < 2; ks++) {
            uint32_t af[2][A_PL][4];
#pragma unroll
            for (int mt = 0; mt < 2; mt++)
#pragma unroll
                for (int pl = 0; pl < A_PL; pl++)
                    ldsm4(af[mt][pl][0], af[mt][pl][1], af[mt][pl][2], af[mt][pl][3],
                          aLd0 + cur + pl * 10240u + mt * 16 * 80 + ks * 32);
            uint32_t bf[B_PL][4][2];
#pragma unroll
            for (int pl = 0; pl < B_PL; pl++)
#pragma unroll
                for (int nt2 = 0; nt2 < 2; nt2++) {
                    uint32_t r0, r1, r2, r3;
                    ldsm4(r0, r1, r2, r3,
                          bLd0 + cur + pl * 5120u + nt2 * 16 * 80 + ks * 32);
                    bf[pl][nt2 * 2][0] = r0; bf[pl][nt2 * 2][1] = r1;
                    bf[pl][nt2 * 2 + 1][0] = r2; bf[pl][nt2 * 2 + 1][1] = r3;
                }
#pragma unroll
            for (int prod = 0; prod < NPROD; prod++) {
                const int apl = (prod == 2) ? 1 : 0;
                const int bpl = (prod == 1) ? 1 : 0;
#pragma unroll
                for (int mt = 0; mt < 2; mt++)
#pragma unroll
                    for (int nt = 0; nt < 4; nt++)
                        mma16816(acc[mt][nt], af[mt][apl], bf[bpl][nt]);
            }
        }
    }

    // ---- epilogue ----
    if (ACT == 2) {
        __syncthreads();
        float* vs = (float*)smem;
        if (wn == 32) {
#pragma unroll
            for (int mt = 0; mt < 2; mt++)
#pragma unroll
                for (int nt = 0; nt < 4; nt++) {
                    int r0 = wm + mt * 16 + (lane >> 2);
                    int c = nt * 8 + (lane & 3) * 2;
                    vs[r0 * 34 + c]           = acc[mt][nt][0] * ISCALE;
                    vs[r0 * 34 + c + 1]       = acc[mt][nt][1] * ISCALE;
                    vs[(r0 + 8) * 34 + c]     = acc[mt][nt][2] * ISCALE;
                    vs[(r0 + 8) * 34 + c + 1] = acc[mt][nt][3] * ISCALE;
                }
        }
        __syncthreads();
        if (wn == 0) {
#pragma unroll
            for (int mt = 0; mt < 2; mt++) {
                int r0 = wm + mt * 16 + (lane >> 2);
                float s0 = rowS[bm + r0];
                float s8 = rowS[bm + r0 + 8];
#pragma unroll
                for (int nt = 0; nt < 4; nt++) {
                    int c = nt * 8 + (lane & 3) * 2;
                    float g0 = acc[mt][nt][0] * ISCALE * s0, g1 = acc[mt][nt][1] * ISCALE * s0;
                    float g2 = acc[mt][nt][2] * ISCALE * s8, g3 = acc[mt][nt][3] * ISCALE * s8;
                    float o0 = g0 / (1.0f + expf(-g0)) * (s0 * vs[r0 * 34 + c]);
                    float o1 = g1 / (1.0f + expf(-g1)) * (s0 * vs[r0 * 34 + c + 1]);
                    float o2 = g2 / (1.0f + expf(-g2)) * (s8 * vs[(r0 + 8) * 34 + c]);
                    float o3 = g3 / (1.0f + expf(-g3)) * (s8 * vs[(r0 + 8) * 34 + c + 1]);
                    size_t row = (size_t)(bm + r0);
                    int col = (bn >> 1) + c;
                    __half h0 = __float2half(o0), h1 = __float2half(o1);
                    __half h2 = __float2half(o2), h3 = __float2half(o3);
                    *(uint32_t*)(Cp + row * Nout + col) =
                        (uint32_t)__half_as_ushort(h0) | ((uint32_t)__half_as_ushort(h1) << 16);
                    *(uint32_t*)(Cp + cPstride + row * Nout + col) =
                        packh(o0 - __half2float(h0), o1 - __half2float(h1));
                    *(uint32_t*)(Cp + (row + 8) * Nout + col) =
                        (uint32_t)__half_as_ushort(h2) | ((uint32_t)__half_as_ushort(h3) << 16);
                    *(uint32_t*)(Cp + cPstride + (row + 8) * Nout + col) =
                        packh(o2 - __half2float(h2), o3 - __half2float(h3));
                }
            }
        }
        return;
    }

    const bool doPlanes = !(OUTMODE & 8) || (bm < MROWS);

#pragma unroll
    for (int mt = 0; mt < 2; mt++) {
        int row0 = bm + wm + mt * 16 + (lane >> 2);
#pragma unroll
        for (int nt = 0; nt < 4; nt++) {
            int col0 = bn + wn + nt * 8 + (lane & 3) * 2;
            float b0 = 0.f, b1 = 0.f;
            if (bias) { b0 = bias[col0]; b1 = bias[col0 + 1]; }
            float o0 = acc[mt][nt][0] * ISCALE + b0;
            float o1 = acc[mt][nt][1] * ISCALE + b1;
            float o2 = acc[mt][nt][2] * ISCALE + b0;
            float o3 = acc[mt][nt][3] * ISCALE + b1;
            if (ACT == 1) {
                o0 = gelu_tanh(o0); o1 = gelu_tanh(o1);
                o2 = gelu_tanh(o2); o3 = gelu_tanh(o3);
            }
            if (OUTMODE & 1) {
                *(float2*)(Cf + (size_t)row0 * Nout + col0) = make_float2(o0, o1);
                *(float2*)(Cf + (size_t)(row0 + 8) * Nout + col0) = make_float2(o2, o3);
            }
            if ((OUTMODE & 2) && doPlanes) {
                __half h0 = __float2half(o0), h1 = __float2half(o1);
                __half h2 = __float2half(o2), h3 = __float2half(o3);
                *(uint32_t*)(Cp + (size_t)row0 * Nout + col0) =
                    (uint32_t)__half_as_ushort(h0) | ((uint32_t)__half_as_ushort(h1) << 16);
                *(uint32_t*)(Cp + cPstride + (size_t)row0 * Nout + col0) =
                    packh(o0 - __half2float(h0), o1 - __half2float(h1));
                *(uint32_t*)(Cp + (size_t)(row0 + 8) * Nout + col0) =
                    (uint32_t)__half_as_ushort(h2) | ((uint32_t)__half_as_ushort(h3) << 16);
                *(uint32_t*)(Cp + cPstride + (size_t)(row0 + 8) * Nout + col0) =
                    packh(o2 - __half2float(h2), o3 - __half2float(h3));
            }
            if (OUTMODE & 4) {
                *(uint32_t*)(Cp + (size_t)row0 * Nout + col0) = packh(o0, o1);
                *(uint32_t*)(Cp + (size_t)(row0 + 8) * Nout + col0) = packh(o2, o3);
            }
        }
    }
}

// ---------------- weight prep ----------------
__global__ void split_kernel(const float* __restrict__ W, __half* __restrict__ out,
                             int n, int pstride)
{
    int i = blockIdx.x * 256 + threadIdx.x;
    if (i >= n) return;
    float r = W[i] * WSCALE;
    __half h = __float2half(r);
    out[i] = h;
    r -= __half2float(h);
    out[(size_t)pstride + i] = __float2half(r);
}

// WabP: interleave Wa/Wb rows in 32-row groups, fold g1[k] into weights
__global__ void swab_split(const float* __restrict__ Wa, const float* __restrict__ Wb,
                           const float* __restrict__ g1, __half* __restrict__ out)
{
    int i = blockIdx.x * 256 + threadIdx.x;   // 262144
    int nrow = i >> 8, k = i & 255;
    int j = nrow >> 6, r = nrow & 63;
    float w = (r < 32) ? Wa[(j * 32 + r) * 256 + k] : Wb[(j * 32 + r - 32) * 256 + k];
    float rr = w * g1[k] * WSCALE;
    __half h = __float2half(rr);
    out[i] = h;
    rr -= __half2float(h);
    out[262144 + i] = __float2half(rr);
}

__global__ void tsplit_kernel(const float* __restrict__ W, __half* __restrict__ out)
{
    int i = blockIdx.x * 256 + threadIdx.x;
    int nrow = i >> 8, k = i & 255;
    float r = W[k * 256 + nrow] * WSCALE;
    __half h = __float2half(r);
    out[i] = h;
    r -= __half2float(h);
    out[65536 + i] = __float2half(r);
}

__global__ void fusew_kernel(const float* __restrict__ W2, const float* __restrict__ Wc,
                             float* __restrict__ Wf)
{
    int idx = blockIdx.x * blockDim.x + threadIdx.x;
    int i = idx >> 9, j = idx & 511;
    float s = 0.0f;
    for (int k = 0; k < 256; k++) s += W2[i * 256 + k] * Wc[k * 512 + j];
    Wf[idx] = s;
}

// ---------------- elementwise ----------------
template <int NC>
__global__ void rmsnorm_kernel(float* __restrict__ x, const float* __restrict__ g, int rows)
{
    int row = blockIdx.x * 8 + (threadIdx.x >> 5);
    int lane = threadIdx.x & 31;
    if (row >= rows) return;
    float* p = x + (size_t)row * NC;
    constexpr int V = NC / 32;
    float v[V];
    float ss = 0.0f;
#pragma unroll
    for (int i = 0; i < V; i++) { v[i] = p[lane + 32 * i]; ss += v[i] * v[i]; }
#pragma unroll
    for (int o = 16; o > 0; o >>= 1) ss += __shfl_xor_sync(0xffffffffu, ss, o);
    float sc = rsqrtf(ss * (1.0f / NC) + 1e-6f);
#pragma unroll
    for (int i = 0; i < V; i++) p[lane + 32 * i] = v[i] * sc * g[lane + 32 * i];
}

// row scales from x1 planes: s[m] = rsqrt(mean((hi+lo)^2) + 1e-6)
__global__ void rowscale_kernel(const __half* __restrict__ xP, float* __restrict__ s, int rows)
{
    int row = blockIdx.x * 8 + (threadIdx.x >> 5);
    int lane = threadIdx.x & 31;
    if (row >= rows) return;
    const __half* ph = xP + (size_t)row * 256;
    const __half* pl = xP + PX1 + (size_t)row * 256;
    float ss = 0.0f;
#pragma unroll
    for (int i = 0; i < 8; i++) {
        float v = __half2float(ph[lane + 32 * i]) + __half2float(pl[lane + 32 * i]);
        ss += v * v;
    }
#pragma unroll
    for (int o = 16; o > 0; o >>= 1) ss += __shfl_xor_sync(0xffffffffu, ss, o);
    if (lane == 0) s[row] = rsqrtf(ss * (1.0f / 256.0f) + 1e-6f);
}

// ---------------- per-batch sinkhorn etc ----------------
__global__ __launch_bounds__(256) void batch_kernel(
    const float* __restrict__ u, const float* __restrict__ tgt,
    const float* __restrict__ src, const float* __restrict__ bbil,
    const float* __restrict__ Wc1, const float* __restrict__ bc1,
    float* __restrict__ out_mapping, float* __restrict__ out_mapped,
    float* __restrict__ out_conf, __half* __restrict__ combP)
{
    const int b = blockIdx.x;
    const int tid = threadIdx.x;
    __shared__ float u_s[RROLE * HDIM];
    __shared__ float t_s[RROLE * HDIM];
    __shared__ float s_s[RROLE * HDIM];
    __shared__ float la[RROLE * RROLE];
    __shared__ float map_s[RROLE * RROLE];
    __shared__ float lse[RROLE];
    __shared__ float red[256];

    const size_t base = (size_t)b * RROLE * HDIM;
    for (int e = tid; e < RROLE * HDIM; e += 256) {
        u_s[e] = u[base + e];
        t_s[e] = tgt[base + e];
        s_s[e] = src[base + e];
    }
    __syncthreads();

    const float bb = bbil[0];
    const int warp = tid >> 5, lane = tid & 31;
    for (int p = warp; p < RROLE * RROLE; p += 8) {
        int i = p / RROLE, j = p % RROLE;
        float d = 0.0f;
        for (int h = lane; h < HDIM; h += 32) d += u_s[i * HDIM + h] * t_s[j * HDIM + h];
#pragma unroll
        for (int o = 16; o > 0; o >>= 1) d += __shfl_xor_sync(0xffffffffu, d, o);
        if (lane == 0) la[p] = (d + bb) * TEMP_INV;
    }
    __syncthreads();

    for (int it = 0; it < SINKHORN_ITERS; it++) {
        if (tid < RROLE) {
            float m = -1e30f;
            for (int j = 0; j < RROLE; j++) m = fmaxf(m, la[tid * RROLE + j]);
            float s = 0.0f;
            for (int j = 0; j < RROLE; j++) s += expf(la[tid * RROLE + j] - m);
            lse[tid] = m + logf(s);
        }
        __syncthreads();
        if (tid < RROLE * RROLE) la[tid] -= lse[tid / RROLE];
        __syncthreads();
        if (tid < RROLE) {
            float m = -1e30f;
            for (int i = 0; i < RROLE; i++) m = fmaxf(m, la[i * RROLE + tid]);
            float s = 0.0f;
            for (int i = 0; i < RROLE; i++) s += expf(la[i * RROLE + tid] - m);
            lse[tid] = m + logf(s);
        }
        __syncthreads();
        if (tid < RROLE * RROLE) la[tid] -= lse[tid % RROLE];
        __syncthreads();
    }

    if (tid < RROLE * RROLE) {
        float mv = expf(la[tid]);
        map_s[tid] = mv;
        out_mapping[(size_t)b * RROLE * RROLE + tid] = mv;
    }
    __syncthreads();

    float local = 0.0f;
    for (int e = tid; e < RROLE * HDIM; e += 256) {
        int i = e >> 8;
        int h = e & 255;
        float v = 0.0f;
#pragma unroll
        for (int j = 0; j < RROLE; j++) v += map_s[i * RROLE + j] * t_s[j * HDIM + h];
        out_mapped[base + e] = v;
        size_t cbase = ((size_t)b * RROLE + i) * 512;
        combP[cbase + h] = __float2half(v);
        combP[cbase + 256 + h] = __float2half(t_s[i * HDIM + h]);
        local += fabsf(v - s_s[e]);
    }
    red[tid] = local;
    __syncthreads();
    for (int s = 128; s > 0; s >>= 1) {
        if (tid < s) red[tid] += red[tid + s];
        __syncthreads();
    }
    if (tid == 0) {
        float conf_in = red[0] * (1.0f / (RROLE * HDIM));
        float z = conf_in * Wc1[0] + bc1[0];
        out_conf[b] = 1.0f / (1.0f + expf(-z));
    }
}

// ---------------- launch ----------------
#define SMEM3 92160
#define SMEM1 61440

extern "C" void kernel_launch(void* const* d_in, const int* in_sizes, int n_in,
                              void* d_out, int out_size)
{
    (void)in_sizes; (void)n_in; (void)out_size;
    const float* src  = (const float*)d_in[0];
    const float* tgt  = (const float*)d_in[1];
    const float* W1   = (const float*)d_in[2];
    const float* b1   = (const float*)d_in[3];
    const float* g1   = (const float*)d_in[4];
    const float* Wa   = (const float*)d_in[5];
    const float* Wb   = (const float*)d_in[6];
    const float* Wc   = (const float*)d_in[7];
    const float* W2   = (const float*)d_in[8];
    const float* b2   = (const float*)d_in[9];
    const float* Wbil = (const float*)d_in[10];
    const float* bbil = (const float*)d_in[11];
    const float* Wa1  = (const float*)d_in[12];
    const float* ba1  = (const float*)d_in[13];
    const float* Wa2  = (const float*)d_in[14];
    const float* ba2  = (const float*)d_in[15];
    const float* g2   = (const float*)d_in[16];
    const float* Wc1  = (const float*)d_in[17];
    const float* bc1  = (const float*)d_in[18];
    float* out = (float*)d_out;

    float *Wf, *enc, *ub, *sArr;
    __half *x1P, *hP, *encP, *combP, *bigP;
    __half *W1P, *WabP, *WfP, *WbTP, *Wa1P, *Wa2P;
    cudaGetSymbolAddress((void**)&Wf,    g_Wf);
    cudaGetSymbolAddress((void**)&enc,   g_enc);
    cudaGetSymbolAddress((void**)&ub,    g_u);
    cudaGetSymbolAddress((void**)&sArr,  g_s);
    cudaGetSymbolAddress((void**)&x1P,   g_x1P);
    cudaGetSymbolAddress((void**)&hP,    g_hP);
    cudaGetSymbolAddress((void**)&encP,  g_encP);
    cudaGetSymbolAddress((void**)&combP, g_combP);
    cudaGetSymbolAddress((void**)&bigP,  g_bigP);
    cudaGetSymbolAddress((void**)&W1P,   g_W1P);
    cudaGetSymbolAddress((void**)&WabP,  g_WabP);
    cudaGetSymbolAddress((void**)&WfP,   g_WfP);
    cudaGetSymbolAddress((void**)&WbTP,  g_WbTP);
    cudaGetSymbolAddress((void**)&Wa1P,  g_Wa1P);
    cudaGetSymbolAddress((void**)&Wa2P,  g_Wa2P);

    cudaFuncSetAttribute(gemm_l1, cudaFuncAttributeMaxDynamicSharedMemorySize, SMEM_L1);
    cudaFuncSetAttribute(gemm_mma<0,11,3>, cudaFuncAttributeMaxDynamicSharedMemorySize, SMEM3);
    cudaFuncSetAttribute(gemm_mma<0,1,3>, cudaFuncAttributeMaxDynamicSharedMemorySize, SMEM3);
    cudaFuncSetAttribute(gemm_mma<2,2,3>, cudaFuncAttributeMaxDynamicSharedMemorySize, SMEM3);
    cudaFuncSetAttribute(gemm_mma<1,4,1>, cudaFuncAttributeMaxDynamicSharedMemorySize, SMEM1);
    cudaFuncSetAttribute(gemm_mma<0,1,1>, cudaFuncAttributeMaxDynamicSharedMemorySize, SMEM1);

    // ---- prep ----
    fusew_kernel<<<512, 256>>>(W2, Wc, Wf);
    split_kernel<<<1024, 256>>>(W1, W1P, 262144, 262144);
    swab_split<<<1024, 256>>>(Wa, Wb, g1, WabP);
    split_kernel<<<512, 256>>>(Wf, WfP, 131072, 131072);
    tsplit_kernel<<<256, 256>>>(Wbil, WbTP);
    split_kernel<<<1024, 256>>>(Wa1, Wa1P, 262144, 262144);
    split_kernel<<<2048, 256>>>(Wa2, Wa2P, 524288, 524288);

    // ---- merged encoder (src rows 0..M-1, tgt rows M..2M-1) ----
    gemm_l1<<<dim3(4, M2 / 128), 256, SMEM_L1>>>(
        src, tgt, W1P, 262144, b1, x1P, 256, 1024, 256);
    rowscale_kernel<<<M2 / 8, 256>>>(x1P, sArr, M2);
    gemm_mma<2,2,3><<<dim3(16, M2 / 128), 256, SMEM3>>>(
        x1P, PX1, WabP, 262144, nullptr, sArr, nullptr, hP, PH, 1024, 256, 512);
    gemm_mma<0,11,3><<<dim3(4, M2 / 128), 256, SMEM3>>>(
        hP, PH, WfP, 131072, b2, nullptr, enc, encP, PE, 256, 512, 256);

    // ---- bilinear u = enc_src @ Wbil (first MROWS rows of encP) ----
    gemm_mma<0,1,3><<<dim3(4, MROWS / 128), 256, SMEM3>>>(
        encP, PE, WbTP, 65536, nullptr, nullptr, ub, nullptr, 0, 256, 256, 256);

    // ---- sinkhorn / mapping / confidence / combined (hi plane only) ----
    batch_kernel<<<BATCH, 256>>>(ub, enc + (size_t)MROWS * 256, enc, bbil, Wc1, bc1,
                                 out + OUT_MAPPING_OFF, out + OUT_MAPPED_OFF,
                                 out + OUT_CONF_OFF, combP);

    // ---- answer projection (1-product path: hi x hi only, 4-stage) ----
    gemm_mma<1,4,1><<<dim3(8, MROWS / 128), 256, SMEM1>>>(
        combP, 0, Wa1P, 262144, ba1, nullptr, nullptr, bigP, 0, 512, 512, 512);
    gemm_mma<0,1,1><<<dim3(16, MROWS / 128), 256, SMEM1>>>(
        bigP, 0, Wa2P, 524288, ba2, nullptr, out + OUT_ANSWER_OFF, nullptr, 0, 1024, 512, 1024);
    rmsnorm_kernel<DDIM><<<MROWS / 8, 256>>>(out + OUT_ANSWER_OFF, g2, MROWS);
}

// round 14
// speedup vs baseline: 1.0183x; 1.0183x over previous
#include <cuda_runtime.h>
#include <cuda_fp16.h>
#include <cstdint>
#include <math.h>

#define BATCH 8192
#define RROLE 6
#define DDIM 1024
#define HDIM 256
#define MROWS (BATCH * RROLE)          // 49152
#define M2 (2 * MROWS)                 // 98304 (src+tgt merged)
#define TEMP_INV 2.0f
#define SINKHORN_ITERS 5

#define OUT_ANSWER_OFF  0
#define OUT_MAPPING_OFF ((size_t)MROWS * DDIM)
#define OUT_MAPPED_OFF  (OUT_MAPPING_OFF + (size_t)BATCH * RROLE * RROLE)
#define OUT_CONF_OFF    (OUT_MAPPED_OFF + (size_t)MROWS * HDIM)

#define WSCALE 1024.0f
#define ISCALE (1.0f / 1024.0f)

// plane strides (elements per plane)
#define PX1  ((size_t)M2 * 256)
#define PH   ((size_t)M2 * 512)
#define PE   ((size_t)M2 * 256)

// ---------------- device scratch ----------------
__device__ float g_x1[(size_t)M2 * 256];
__device__ float g_enc[(size_t)M2 * 256];          // rows 0..M-1 src, M..2M-1 tgt
__device__ float g_u[(size_t)MROWS * 256];

__device__ __half g_x1P  [2 * (size_t)M2 * 256];
__device__ __half g_hP   [2 * (size_t)M2 * 512];
__device__ __half g_encP [2 * (size_t)M2 * 256];
__device__ __half g_combP[(size_t)MROWS * 512];    // hi plane only (answer path)
__device__ __half g_bigP [(size_t)MROWS * 512];    // hi plane only

// fp16 weight planes (2 planes each, scaled by WSCALE)
__device__ __half g_W1P [2 * 256 * 1024];
__device__ __half g_WabP[2 * 1024 * 256];   // interleaved gate/value rows
__device__ __half g_WfP [2 * 256 * 512];
__device__ __half g_WbTP[2 * 256 * 256];
__device__ __half g_Wa1P[2 * 512 * 512];
__device__ __half g_Wa2P[2 * 1024 * 512];

// ---------------- helpers ----------------
__device__ __forceinline__ uint32_t smem_u32(const void* p) {
    uint32_t a;
    asm("{ .reg .u64 t; cvta.to.shared.u64 t, %1; cvt.u32.u64 %0, t; }" : "=r"(a) : "l"(p));
    return a;
}
__device__ __forceinline__ float gelu_tanh(float x) {
    float x3 = x * x * x;
    return 0.5f * x * (1.0f + tanhf(0.7978845608028654f * (x + 0.044715f * x3)));
}
__device__ __forceinline__ void ldsm4(uint32_t& r0, uint32_t& r1, uint32_t& r2, uint32_t& r3,
                                      uint32_t addr) {
    asm volatile("ldmatrix.sync.aligned.m8n8.x4.shared.b16 {%0,%1,%2,%3}, [%4];"
                 : "=r"(r0), "=r"(r1), "=r"(r2), "=r"(r3) : "r"(addr));
}
__device__ __forceinline__ void mma16816(float* c, const uint32_t* a, const uint32_t* b) {
    asm volatile("mma.sync.aligned.m16n8k16.row.col.f32.f16.f16.f32 "
                 "{%0,%1,%2,%3}, {%4,%5,%6,%7}, {%8,%9}, {%0,%1,%2,%3};"
                 : "+f"(c[0]), "+f"(c[1]), "+f"(c[2]), "+f"(c[3])
                 : "r"(a[0]), "r"(a[1]), "r"(a[2]), "r"(a[3]), "r"(b[0]), "r"(b[1]));
}
__device__ __forceinline__ uint32_t packh(float x, float y) {
    __half h0 = __float2half(x), h1 = __float2half(y);
    return (uint32_t)__half_as_ushort(h0) | ((uint32_t)__half_as_ushort(h1) << 16);
}
#define CP_ASYNC16(dst, src) \
    asm volatile("cp.async.cg.shared.global [%0], [%1], 16;" :: "r"(dst), "l"(src) : "memory")
#define CP_COMMIT() asm volatile("cp.async.commit_group;" ::: "memory")
#define CP_WAIT0()  asm volatile("cp.async.wait_group 0;" ::: "memory")
#define CP_WAIT1()  asm volatile("cp.async.wait_group 1;" ::: "memory")
#define CP_WAIT2()  asm volatile("cp.async.wait_group 2;" ::: "memory")

// ---------------- layer1 GEMM: fp32 A, in-kernel split, 2-stage ----------------
#define GBUF 30720
#define SMEM_L1 61440

__global__ __launch_bounds__(256, 2) void gemm_l1(
    const float* __restrict__ Asrc, const float* __restrict__ Atgt,
    const __half* __restrict__ Bp, size_t bPstride,
    const float* __restrict__ bias, float* __restrict__ Cf,
    int N, int K, int Nout)
{
    extern __shared__ char smem[];
    const uint32_t sb = smem_u32(smem);
    const int tid = threadIdx.x, lane = tid & 31, wid = tid >> 5;
    const int bm = blockIdx.y * 128, bn = blockIdx.x * 64;
    const int wm = (wid >> 1) * 32, wn = (wid & 1) * 32;

    const float* A = (bm < MROWS) ? Asrc : (Atgt - (size_t)MROWS * K);

    const uint32_t aLd0 = sb + (uint32_t)((wm + (lane & 15)) * 80 + (lane >> 4) * 16);
    const uint32_t bLd0 = sb + 20480u +
        (uint32_t)(((wn + (lane & 7) + ((lane >> 4) & 1) * 8) * 80) + ((lane >> 3) & 1) * 16);

    float acc[2][4][4];
#pragma unroll
    for (int mt = 0; mt < 2; mt++)
#pragma unroll
        for (int nt = 0; nt < 4; nt++)
#pragma unroll
            for (int i = 0; i < 4; i++) acc[mt][nt][i] = 0.0f;

    const int nkb = K >> 5;

    const int arow = tid >> 1, acol = (tid & 1) * 16;
    const float* aBase = A + (size_t)(bm + arow) * K + acol;
    const uint32_t aStsOff = (uint32_t)(arow * 80 + acol * 2);
    const int brow = tid >> 2, bseg = tid & 3;
    const __half* bBase = Bp + (size_t)(bn + brow) * K + bseg * 8;
    const uint32_t bSts = sb + 20480u + (uint32_t)(brow * 80 + bseg * 16);

    {
        float v[16];
#pragma unroll
        for (int j = 0; j < 4; j++)
            *(float4*)(v + j * 4) = *(const float4*)(aBase + j * 4);
        uint32_t hp[8], lp[8];
#pragma unroll
        for (int j = 0; j < 8; j++) {
            __half h0 = __float2half(v[2 * j]), h1 = __float2half(v[2 * j + 1]);
            hp[j] = (uint32_t)__half_as_ushort(h0) | ((uint32_t)__half_as_ushort(h1) << 16);
            lp[j] = packh(v[2 * j] - __half2float(h0), v[2 * j + 1] - __half2float(h1));
        }
        *(uint4*)(smem + aStsOff)              = *(uint4*)hp;
        *(uint4*)(smem + aStsOff + 16)         = *(uint4*)(hp + 4);
        *(uint4*)(smem + aStsOff + 10240)      = *(uint4*)lp;
        *(uint4*)(smem + aStsOff + 10240 + 16) = *(uint4*)(lp + 4);
#pragma unroll
        for (int pl = 0; pl < 2; pl++)
            CP_ASYNC16(bSts + pl * 5120u, bBase + (size_t)pl * bPstride);
        CP_COMMIT();
        CP_WAIT0();
        __syncthreads();
    }

    for (int kb = 0; kb < nkb; kb++) {
        const uint32_t cur = (uint32_t)(kb & 1) * GBUF;
        const uint32_t nxt = (uint32_t)((kb + 1) & 1) * GBUF;
        const bool has = (kb + 1) < nkb;

        float vstage[16];
        if (has) {
            const float* ap = aBase + (kb + 1) * 32;
#pragma unroll
            for (int j = 0; j < 4; j++)
                *(float4*)(vstage + j * 4) = *(const float4*)(ap + j * 4);
            const __half* bp = bBase + (kb + 1) * 32;
#pragma unroll
            for (int pl = 0; pl < 2; pl++)
                CP_ASYNC16(bSts + nxt + pl * 5120u, bp + (size_t)pl * bPstride);
        }
        CP_COMMIT();

#pragma unroll
        for (int ks = 0; ks < 2; ks++) {
            uint32_t af[2][2][4];
#pragma unroll
            for (int mt = 0; mt < 2; mt++)
#pragma unroll
                for (int pl = 0; pl < 2; pl++)
                    ldsm4(af[mt][pl][0], af[mt][pl][1], af[mt][pl][2], af[mt][pl][3],
                          aLd0 + cur + pl * 10240u + mt * 16 * 80 + ks * 32);
            uint32_t bf[2][4][2];
#pragma unroll
            for (int pl = 0; pl < 2; pl++)
#pragma unroll
                for (int nt2 = 0; nt2 < 2; nt2++) {
                    uint32_t r0, r1, r2, r3;
                    ldsm4(r0, r1, r2, r3,
                          bLd0 + cur + pl * 5120u + nt2 * 16 * 80 + ks * 32);
                    bf[pl][nt2 * 2][0] = r0; bf[pl][nt2 * 2][1] = r1;
                    bf[pl][nt2 * 2 + 1][0] = r2; bf[pl][nt2 * 2 + 1][1] = r3;
                }
#pragma unroll
            for (int prod = 0; prod < 3; prod++) {
                const int apl = (prod == 2) ? 1 : 0;
                const int bpl = (prod == 1) ? 1 : 0;
#pragma unroll
                for (int mt = 0; mt < 2; mt++)
#pragma unroll
                    for (int nt = 0; nt < 4; nt++)
                        mma16816(acc[mt][nt], af[mt][apl], bf[bpl][nt]);
            }
        }

        if (has) {
            uint32_t hp[8], lp[8];
#pragma unroll
            for (int j = 0; j < 8; j++) {
                __half h0 = __float2half(vstage[2 * j]), h1 = __float2half(vstage[2 * j + 1]);
                hp[j] = (uint32_t)__half_as_ushort(h0) | ((uint32_t)__half_as_ushort(h1) << 16);
                lp[j] = packh(vstage[2 * j] - __half2float(h0), vstage[2 * j + 1] - __half2float(h1));
            }
            uint32_t off = aStsOff + nxt;
            *(uint4*)(smem + off)              = *(uint4*)hp;
            *(uint4*)(smem + off + 16)         = *(uint4*)(hp + 4);
            *(uint4*)(smem + off + 10240)      = *(uint4*)lp;
            *(uint4*)(smem + off + 10240 + 16) = *(uint4*)(lp + 4);
        }
        CP_WAIT0();
        __syncthreads();
    }

#pragma unroll
    for (int mt = 0; mt < 2; mt++) {
        int row0 = bm + wm + mt * 16 + (lane >> 2);
#pragma unroll
        for (int nt = 0; nt < 4; nt++) {
            int col0 = bn + wn + nt * 8 + (lane & 3) * 2;
            float b0 = bias[col0], b1 = bias[col0 + 1];
            *(float2*)(Cf + (size_t)row0 * Nout + col0) =
                make_float2(acc[mt][nt][0] * ISCALE + b0, acc[mt][nt][1] * ISCALE + b1);
            *(float2*)(Cf + (size_t)(row0 + 8) * Nout + col0) =
                make_float2(acc[mt][nt][2] * ISCALE + b0, acc[mt][nt][3] * ISCALE + b1);
        }
    }
}

// ---------------- HMMA GEMM (multi-stage pipelined, fp16-plane A) ----------------
// NPROD=3: A 2 planes, B 2 planes, hh+hl+lh (3 stages).
// NPROD=1: A hi, B hi, hh only (4 stages).
// ACT: 0 none, 1 gelu, 2 swiglu. OUTMODE bit0 fp32, bit1 fp16 hi+lo, bit2 fp16 hi,
// bit3: plane outputs only for rows < MROWS.
template <int ACT, int OUTMODE, int NPROD>
__global__ __launch_bounds__(256, 2) void gemm_mma(
    const __half* __restrict__ Ap, size_t aPstride,
    const __half* __restrict__ Bp, size_t bPstride,
    const float* __restrict__ bias,
    float* __restrict__ Cf,
    __half* __restrict__ Cp, size_t cPstride,
    int N, int K, int Nout)
{
    constexpr int A_PL = (NPROD == 3) ? 2 : 1;
    constexpr int B_PL = (NPROD >= 2) ? 2 : 1;
    constexpr uint32_t ASZ = A_PL * 10240u;
    constexpr uint32_t STG_SZ = ASZ + B_PL * 5120u;
    constexpr int NSTG = (NPROD == 1) ? 4 : 3;

    extern __shared__ char smem[];
    const uint32_t sb = smem_u32(smem);
    const int tid = threadIdx.x, lane = tid & 31, wid = tid >> 5;
    const int bm = blockIdx.y * 128, bn = blockIdx.x * 64;
    const int wm = (wid >> 1) * 32, wn = (wid & 1) * 32;

    const uint32_t aLd0 = sb + (uint32_t)((wm + (lane & 15)) * 80 + (lane >> 4) * 16);
    const uint32_t bLd0 = sb + ASZ +
        (uint32_t)(((wn + (lane & 7) + ((lane >> 4) & 1) * 8) * 80) + ((lane >> 3) & 1) * 16);

    float acc[2][4][4];
#pragma unroll
    for (int mt = 0; mt < 2; mt++)
#pragma unroll
        for (int nt = 0; nt < 4; nt++)
#pragma unroll
            for (int i = 0; i < 4; i++) acc[mt][nt][i] = 0.0f;

    const int nkb = K >> 5;

    auto issue = [&](int kidx, uint32_t base) {
#pragma unroll
        for (int t = 0; t < 2 * A_PL; t++) {
            int idx = t * 256 + tid;
            int pl = idx >> 9, row = (idx >> 2) & 127, s = idx & 3;
            const __half* srcp = Ap + (size_t)pl * aPstride + (size_t)(bm + row) * K
                                 + kidx * 32 + s * 8;
            CP_ASYNC16(base + pl * 10240u + row * 80u + s * 16u, srcp);
        }
#pragma unroll
        for (int t = 0; t < B_PL; t++) {
            int idx = t * 256 + tid;
            int pl = idx >> 8, row = (idx >> 2) & 63, s = idx & 3;
            const __half* srcp = Bp + (size_t)pl * bPstride + (size_t)(bn + row) * K
                                 + kidx * 32 + s * 8;
            CP_ASYNC16(base + ASZ + pl * 5120u + row * 80u + s * 16u, srcp);
        }
    };

    issue(0, sb);
    CP_COMMIT();
#pragma unroll
    for (int s = 1; s < NSTG - 1; s++) {
        if (nkb > s) issue(s, sb + s * STG_SZ);
        CP_COMMIT();
    }

    uint32_t curStage = 0;
    for (int kb = 0; kb < nkb; kb++) {
        if (NSTG == 3) CP_WAIT1(); else CP_WAIT2();
        __syncthreads();
        const uint32_t cur = curStage * STG_SZ;
        uint32_t nxtStage = curStage + (NSTG - 1);
        if (nxtStage >= NSTG) nxtStage -= NSTG;
        if (kb + NSTG - 1 < nkb) issue(kb + NSTG - 1, sb + nxtStage * STG_SZ);
        CP_COMMIT();
        curStage = (curStage + 1 == NSTG) ? 0 : curStage + 1;

#pragma unroll
        for (int ks = 0; ks < 2; ks++) {
            uint32_t af[2][A_PL][4];
#pragma unroll
            for (int mt = 0; mt < 2; mt++)
#pragma unroll
                for (int pl = 0; pl < A_PL; pl++)
                    ldsm4(af[mt][pl][0], af[mt][pl][1], af[mt][pl][2], af[mt][pl][3],
                          aLd0 + cur + pl * 10240u + mt * 16 * 80 + ks * 32);
            uint32_t bf[B_PL][4][2];
#pragma unroll
            for (int pl = 0; pl < B_PL; pl++)
#pragma unroll
                for (int nt2 = 0; nt2 < 2; nt2++) {
                    uint32_t r0, r1, r2, r3;
                    ldsm4(r0, r1, r2, r3,
                          bLd0 + cur + pl * 5120u + nt2 * 16 * 80 + ks * 32);
                    bf[pl][nt2 * 2][0] = r0; bf[pl][nt2 * 2][1] = r1;
                    bf[pl][nt2 * 2 + 1][0] = r2; bf[pl][nt2 * 2 + 1][1] = r3;
                }
#pragma unroll
            for (int prod = 0; prod < NPROD; prod++) {
                const int apl = (prod == 2) ? 1 : 0;
                const int bpl = (prod == 1) ? 1 : 0;
#pragma unroll
                for (int mt = 0; mt < 2; mt++)
#pragma unroll
                    for (int nt = 0; nt < 4; nt++)
                        mma16816(acc[mt][nt], af[mt][apl], bf[bpl][nt]);
            }
        }
    }

    // ---- epilogue ----
    if (ACT == 2) {
        __syncthreads();
        float* vs = (float*)smem;
        if (wn == 32) {
#pragma unroll
            for (int mt = 0; mt < 2; mt++)
#pragma unroll
                for (int nt = 0; nt < 4; nt++) {
                    int r0 = wm + mt * 16 + (lane >> 2);
                    int c = nt * 8 + (lane & 3) * 2;
                    vs[r0 * 34 + c]           = acc[mt][nt][0] * ISCALE;
                    vs[r0 * 34 + c + 1]       = acc[mt][nt][1] * ISCALE;
                    vs[(r0 + 8) * 34 + c]     = acc[mt][nt][2] * ISCALE;
                    vs[(r0 + 8) * 34 + c + 1] = acc[mt][nt][3] * ISCALE;
                }
        }
        __syncthreads();
        if (wn == 0) {
#pragma unroll
            for (int mt = 0; mt < 2; mt++) {
                int r0 = wm + mt * 16 + (lane >> 2);
#pragma unroll
                for (int nt = 0; nt < 4; nt++) {
                    int c = nt * 8 + (lane & 3) * 2;
                    float g0 = acc[mt][nt][0] * ISCALE, g1 = acc[mt][nt][1] * ISCALE;
                    float g2 = acc[mt][nt][2] * ISCALE, g3 = acc[mt][nt][3] * ISCALE;
                    float o0 = g0 / (1.0f + expf(-g0)) * vs[r0 * 34 + c];
                    float o1 = g1 / (1.0f + expf(-g1)) * vs[r0 * 34 + c + 1];
                    float o2 = g2 / (1.0f + expf(-g2)) * vs[(r0 + 8) * 34 + c];
                    float o3 = g3 / (1.0f + expf(-g3)) * vs[(r0 + 8) * 34 + c + 1];
                    size_t row = (size_t)(bm + r0);
                    int col = (bn >> 1) + c;
                    __half h0 = __float2half(o0), h1 = __float2half(o1);
                    __half h2 = __float2half(o2), h3 = __float2half(o3);
                    *(uint32_t*)(Cp + row * Nout + col) =
                        (uint32_t)__half_as_ushort(h0) | ((uint32_t)__half_as_ushort(h1) << 16);
                    *(uint32_t*)(Cp + cPstride + row * Nout + col) =
                        packh(o0 - __half2float(h0), o1 - __half2float(h1));
                    *(uint32_t*)(Cp + (row + 8) * Nout + col) =
                        (uint32_t)__half_as_ushort(h2) | ((uint32_t)__half_as_ushort(h3) << 16);
                    *(uint32_t*)(Cp + cPstride + (row + 8) * Nout + col) =
                        packh(o2 - __half2float(h2), o3 - __half2float(h3));
                }
            }
        }
        return;
    }

    const bool doPlanes = !(OUTMODE & 8) || (bm < MROWS);

#pragma unroll
    for (int mt = 0; mt < 2; mt++) {
        int row0 = bm + wm + mt * 16 + (lane >> 2);
#pragma unroll
        for (int nt = 0; nt < 4; nt++) {
            int col0 = bn + wn + nt * 8 + (lane & 3) * 2;
            float b0 = 0.f, b1 = 0.f;
            if (bias) { b0 = bias[col0]; b1 = bias[col0 + 1]; }
            float o0 = acc[mt][nt][0] * ISCALE + b0;
            float o1 = acc[mt][nt][1] * ISCALE + b1;
            float o2 = acc[mt][nt][2] * ISCALE + b0;
            float o3 = acc[mt][nt][3] * ISCALE + b1;
            if (ACT == 1) {
                o0 = gelu_tanh(o0); o1 = gelu_tanh(o1);
                o2 = gelu_tanh(o2); o3 = gelu_tanh(o3);
            }
            if (OUTMODE & 1) {
                *(float2*)(Cf + (size_t)row0 * Nout + col0) = make_float2(o0, o1);
                *(float2*)(Cf + (size_t)(row0 + 8) * Nout + col0) = make_float2(o2, o3);
            }
            if ((OUTMODE & 2) && doPlanes) {
                __half h0 = __float2half(o0), h1 = __float2half(o1);
                __half h2 = __float2half(o2), h3 = __float2half(o3);
                *(uint32_t*)(Cp + (size_t)row0 * Nout + col0) =
                    (uint32_t)__half_as_ushort(h0) | ((uint32_t)__half_as_ushort(h1) << 16);
                *(uint32_t*)(Cp + cPstride + (size_t)row0 * Nout + col0) =
                    packh(o0 - __half2float(h0), o1 - __half2float(h1));
                *(uint32_t*)(Cp + (size_t)(row0 + 8) * Nout + col0) =
                    (uint32_t)__half_as_ushort(h2) | ((uint32_t)__half_as_ushort(h3) << 16);
                *(uint32_t*)(Cp + cPstride + (size_t)(row0 + 8) * Nout + col0) =
                    packh(o2 - __half2float(h2), o3 - __half2float(h3));
            }
            if (OUTMODE & 4) {
                *(uint32_t*)(Cp + (size_t)row0 * Nout + col0) = packh(o0, o1);
                *(uint32_t*)(Cp + (size_t)(row0 + 8) * Nout + col0) = packh(o2, o3);
            }
        }
    }
}

// ---------------- merged weight prep (single launch, region dispatch) ----------------
// regions (element index i over 1,507,328):
// [0,262144)        W1P   [262144,524288) WabP   [524288,655360) WfP (dot+split)
// [655360,720896)   WbTP  [720896,983040) Wa1P   [983040,1507328) Wa2P
__global__ void prep_kernel(
    const float* __restrict__ W1, const float* __restrict__ Wa,
    const float* __restrict__ Wb, const float* __restrict__ W2,
    const float* __restrict__ Wc, const float* __restrict__ Wbil,
    const float* __restrict__ Wa1, const float* __restrict__ Wa2,
    __half* __restrict__ W1P, __half* __restrict__ WabP,
    __half* __restrict__ WfP, __half* __restrict__ WbTP,
    __half* __restrict__ Wa1P, __half* __restrict__ Wa2P)
{
    int i = blockIdx.x * 256 + threadIdx.x;
    float w;
    __half* out;
    int pstride, local;

    if (i < 262144) {                      // W1
        local = i; w = W1[local]; out = W1P; pstride = 262144;
    } else if (i < 524288) {               // Wab interleave
        local = i - 262144;
        int nrow = local >> 8, k = local & 255;
        int j = nrow >> 6, r = nrow & 63;
        w = (r < 32) ? Wa[(j * 32 + r) * 256 + k] : Wb[(j * 32 + r - 32) * 256 + k];
        out = WabP; pstride = 262144;
    } else if (i < 655360) {               // Wf = W2 @ Wc (dot) then split
        local = i - 524288;
        int r = local >> 9, c = local & 511;
        float s = 0.0f;
        for (int k = 0; k < 256; k++) s += W2[r * 256 + k] * Wc[k * 512 + c];
        w = s; out = WfP; pstride = 131072;
    } else if (i < 720896) {               // Wbil transposed
        local = i - 655360;
        int nrow = local >> 8, k = local & 255;
        w = Wbil[k * 256 + nrow];
        out = WbTP; pstride = 65536;
    } else if (i < 983040) {               // Wa1
        local = i - 720896; w = Wa1[local]; out = Wa1P; pstride = 262144;
    } else {                               // Wa2
        local = i - 983040; w = Wa2[local]; out = Wa2P; pstride = 524288;
    }

    float r = w * WSCALE;
    __half h = __float2half(r);
    out[local] = h;
    r -= __half2float(h);
    out[(size_t)pstride + local] = __float2half(r);
}

// ---------------- elementwise ----------------
template <int NC>
__global__ void rmsnorm_kernel(float* __restrict__ x, const float* __restrict__ g, int rows)
{
    int row = blockIdx.x * 8 + (threadIdx.x >> 5);
    int lane = threadIdx.x & 31;
    if (row >= rows) return;
    float* p = x + (size_t)row * NC;
    constexpr int V = NC / 32;
    float v[V];
    float ss = 0.0f;
#pragma unroll
    for (int i = 0; i < V; i++) { v[i] = p[lane + 32 * i]; ss += v[i] * v[i]; }
#pragma unroll
    for (int o = 16; o > 0; o >>= 1) ss += __shfl_xor_sync(0xffffffffu, ss, o);
    float sc = rsqrtf(ss * (1.0f / NC) + 1e-6f);
#pragma unroll
    for (int i = 0; i < V; i++) p[lane + 32 * i] = v[i] * sc * g[lane + 32 * i];
}

__global__ void rmsnorm_planes(const float* __restrict__ x, const float* __restrict__ g,
                               __half* __restrict__ out, int rows)
{
    int row = blockIdx.x * 8 + (threadIdx.x >> 5);
    int lane = threadIdx.x & 31;
    if (row >= rows) return;
    const float* p = x + (size_t)row * 256;
    float v[8];
    float ss = 0.0f;
#pragma unroll
    for (int i = 0; i < 8; i++) { v[i] = p[lane + 32 * i]; ss += v[i] * v[i]; }
#pragma unroll
    for (int o = 16; o > 0; o >>= 1) ss += __shfl_xor_sync(0xffffffffu, ss, o);
    float sc = rsqrtf(ss * (1.0f / 256.0f) + 1e-6f);
#pragma unroll
    for (int i = 0; i < 8; i++) {
        float o = v[i] * sc * g[lane + 32 * i];
        __half h = __float2half(o);
        out[(size_t)row * 256 + lane + 32 * i] = h;
        out[PX1 + (size_t)row * 256 + lane + 32 * i] = __float2half(o - __half2float(h));
    }
}

// ---------------- per-batch sinkhorn etc ----------------
__global__ __launch_bounds__(256) void batch_kernel(
    const float* __restrict__ u, const float* __restrict__ tgt,
    const float* __restrict__ src, const float* __restrict__ bbil,
    const float* __restrict__ Wc1, const float* __restrict__ bc1,
    float* __restrict__ out_mapping, float* __restrict__ out_mapped,
    float* __restrict__ out_conf, __half* __restrict__ combP)
{
    const int b = blockIdx.x;
    const int tid = threadIdx.x;
    __shared__ float u_s[RROLE * HDIM];
    __shared__ float t_s[RROLE * HDIM];
    __shared__ float s_s[RROLE * HDIM];
    __shared__ float la[RROLE * RROLE];
    __shared__ float map_s[RROLE * RROLE];
    __shared__ float lse[RROLE];
    __shared__ float red[256];

    const size_t base = (size_t)b * RROLE * HDIM;
    for (int e = tid; e < RROLE * HDIM; e += 256) {
        u_s[e] = u[base + e];
        t_s[e] = tgt[base + e];
        s_s[e] = src[base + e];
    }
    __syncthreads();

    const float bb = bbil[0];
    const int warp = tid >> 5, lane = tid & 31;
    for (int p = warp; p < RROLE * RROLE; p += 8) {
        int i = p / RROLE, j = p % RROLE;
        float d = 0.0f;
        for (int h = lane; h < HDIM; h += 32) d += u_s[i * HDIM + h] * t_s[j * HDIM + h];
#pragma unroll
        for (int o = 16; o > 0; o >>= 1) d += __shfl_xor_sync(0xffffffffu, d, o);
        if (lane == 0) la[p] = (d + bb) * TEMP_INV;
    }
    __syncthreads();

    for (int it = 0; it < SINKHORN_ITERS; it++) {
        if (tid < RROLE) {
            float m = -1e30f;
            for (int j = 0; j < RROLE; j++) m = fmaxf(m, la[tid * RROLE + j]);
            float s = 0.0f;
            for (int j = 0; j < RROLE; j++) s += expf(la[tid * RROLE + j] - m);
            lse[tid] = m + logf(s);
        }
        __syncthreads();
        if (tid < RROLE * RROLE) la[tid] -= lse[tid / RROLE];
        __syncthreads();
        if (tid < RROLE) {
            float m = -1e30f;
            for (int i = 0; i < RROLE; i++) m = fmaxf(m, la[i * RROLE + tid]);
            float s = 0.0f;
            for (int i = 0; i < RROLE; i++) s += expf(la[i * RROLE + tid] - m);
            lse[tid] = m + logf(s);
        }
        __syncthreads();
        if (tid < RROLE * RROLE) la[tid] -= lse[tid % RROLE];
        __syncthreads();
    }

    if (tid < RROLE * RROLE) {
        float mv = expf(la[tid]);
        map_s[tid] = mv;
        out_mapping[(size_t)b * RROLE * RROLE + tid] = mv;
    }
    __syncthreads();

    float local = 0.0f;
    for (int e = tid; e < RROLE * HDIM; e += 256) {
        int i = e >> 8;
        int h = e & 255;
        float v = 0.0f;
#pragma unroll
        for (int j = 0; j < RROLE; j++) v += map_s[i * RROLE + j] * t_s[j * HDIM + h];
        out_mapped[base + e] = v;
        size_t cbase = ((size_t)b * RROLE + i) * 512;
        combP[cbase + h] = __float2half(v);
        combP[cbase + 256 + h] = __float2half(t_s[i * HDIM + h]);
        local += fabsf(v - s_s[e]);
    }
    red[tid] = local;
    __syncthreads();
    for (int s = 128; s > 0; s >>= 1) {
        if (tid < s) red[tid] += red[tid + s];
        __syncthreads();
    }
    if (tid == 0) {
        float conf_in = red[0] * (1.0f / (RROLE * HDIM));
        float z = conf_in * Wc1[0] + bc1[0];
        out_conf[b] = 1.0f / (1.0f + expf(-z));
    }
}

// ---------------- launch ----------------
#define SMEM3 92160
#define SMEM1 61440

extern "C" void kernel_launch(void* const* d_in, const int* in_sizes, int n_in,
                              void* d_out, int out_size)
{
    (void)in_sizes; (void)n_in; (void)out_size;
    const float* src  = (const float*)d_in[0];
    const float* tgt  = (const float*)d_in[1];
    const float* W1   = (const float*)d_in[2];
    const float* b1   = (const float*)d_in[3];
    const float* g1   = (const float*)d_in[4];
    const float* Wa   = (const float*)d_in[5];
    const float* Wb   = (const float*)d_in[6];
    const float* Wc   = (const float*)d_in[7];
    const float* W2   = (const float*)d_in[8];
    const float* b2   = (const float*)d_in[9];
    const float* Wbil = (const float*)d_in[10];
    const float* bbil = (const float*)d_in[11];
    const float* Wa1  = (const float*)d_in[12];
    const float* ba1  = (const float*)d_in[13];
    const float* Wa2  = (const float*)d_in[14];
    const float* ba2  = (const float*)d_in[15];
    const float* g2   = (const float*)d_in[16];
    const float* Wc1  = (const float*)d_in[17];
    const float* bc1  = (const float*)d_in[18];
    float* out = (float*)d_out;

    float *x1, *enc, *ub;
    __half *x1P, *hP, *encP, *combP, *bigP;
    __half *W1P, *WabP, *WfP, *WbTP, *Wa1P, *Wa2P;
    cudaGetSymbolAddress((void**)&x1,    g_x1);
    cudaGetSymbolAddress((void**)&enc,   g_enc);
    cudaGetSymbolAddress((void**)&ub,    g_u);
    cudaGetSymbolAddress((void**)&x1P,   g_x1P);
    cudaGetSymbolAddress((void**)&hP,    g_hP);
    cudaGetSymbolAddress((void**)&encP,  g_encP);
    cudaGetSymbolAddress((void**)&combP, g_combP);
    cudaGetSymbolAddress((void**)&bigP,  g_bigP);
    cudaGetSymbolAddress((void**)&W1P,   g_W1P);
    cudaGetSymbolAddress((void**)&WabP,  g_WabP);
    cudaGetSymbolAddress((void**)&WfP,   g_WfP);
    cudaGetSymbolAddress((void**)&WbTP,  g_WbTP);
    cudaGetSymbolAddress((void**)&Wa1P,  g_Wa1P);
    cudaGetSymbolAddress((void**)&Wa2P,  g_Wa2P);

    cudaFuncSetAttribute(gemm_l1, cudaFuncAttributeMaxDynamicSharedMemorySize, SMEM_L1);
    cudaFuncSetAttribute(gemm_mma<0,11,3>, cudaFuncAttributeMaxDynamicSharedMemorySize, SMEM3);
    cudaFuncSetAttribute(gemm_mma<0,1,3>, cudaFuncAttributeMaxDynamicSharedMemorySize, SMEM3);
    cudaFuncSetAttribute(gemm_mma<2,2,3>, cudaFuncAttributeMaxDynamicSharedMemorySize, SMEM3);
    cudaFuncSetAttribute(gemm_mma<1,4,1>, cudaFuncAttributeMaxDynamicSharedMemorySize, SMEM1);
    cudaFuncSetAttribute(gemm_mma<0,1,1>, cudaFuncAttributeMaxDynamicSharedMemorySize, SMEM1);

    // ---- merged weight prep (single launch; 1,507,328 elements) ----
    prep_kernel<<<5888, 256>>>(W1, Wa, Wb, W2, Wc, Wbil, Wa1, Wa2,
                               W1P, WabP, WfP, WbTP, Wa1P, Wa2P);

    // ---- merged encoder (src rows 0..M-1, tgt rows M..2M-1) ----
    gemm_l1<<<dim3(4, M2 / 128), 256, SMEM_L1>>>(
        src, tgt, W1P, 262144, b1, x1, 256, 1024, 256);
    rmsnorm_planes<<<M2 / 8, 256>>>(x1, g1, x1P, M2);
    gemm_mma<2,2,3><<<dim3(16, M2 / 128), 256, SMEM3>>>(
        x1P, PX1, WabP, 262144, nullptr, nullptr, hP, PH, 1024, 256, 512);
    gemm_mma<0,11,3><<<dim3(4, M2 / 128), 256, SMEM3>>>(
        hP, PH, WfP, 131072, b2, enc, encP, PE, 256, 512, 256);

    // ---- bilinear u = enc_src @ Wbil (first MROWS rows of encP) ----
    gemm_mma<0,1,3><<<dim3(4, MROWS / 128), 256, SMEM3>>>(
        encP, PE, WbTP, 65536, nullptr, ub, nullptr, 0, 256, 256, 256);

    // ---- sinkhorn / mapping / confidence / combined (hi plane only) ----
    batch_kernel<<<BATCH, 256>>>(ub, enc + (size_t)MROWS * 256, enc, bbil, Wc1, bc1,
                                 out + OUT_MAPPING_OFF, out + OUT_MAPPED_OFF,
                                 out + OUT_CONF_OFF, combP);

    // ---- answer projection (1-product path: hi x hi only, 4-stage) ----
    gemm_mma<1,4,1><<<dim3(8, MROWS / 128), 256, SMEM1>>>(
        combP, 0, Wa1P, 262144, ba1, nullptr, bigP, 0, 512, 512, 512);
    gemm_mma<0,1,1><<<dim3(16, MROWS / 128), 256, SMEM1>>>(
        bigP, 0, Wa2P, 524288, ba2, out + OUT_ANSWER_OFF, nullptr, 0, 1024, 512, 1024);
    rmsnorm_kernel<DDIM><<<MROWS / 8, 256>>>(out + OUT_ANSWER_OFF, g2, MROWS);
}

// round 15
// speedup vs baseline: 1.0817x; 1.0623x over previous
#include <cuda_runtime.h>
#include <cuda_fp16.h>
#include <cstdint>
#include <math.h>

#define BATCH 8192
#define RROLE 6
#define DDIM 1024
#define HDIM 256
#define MROWS (BATCH * RROLE)          // 49152
#define M2 (2 * MROWS)                 // 98304 (src+tgt merged)
#define TEMP_INV 2.0f
#define SINKHORN_ITERS 5

#define OUT_ANSWER_OFF  0
#define OUT_MAPPING_OFF ((size_t)MROWS * DDIM)
#define OUT_MAPPED_OFF  (OUT_MAPPING_OFF + (size_t)BATCH * RROLE * RROLE)
#define OUT_CONF_OFF    (OUT_MAPPED_OFF + (size_t)MROWS * HDIM)

#define WSCALE 1024.0f
#define ISCALE (1.0f / 1024.0f)

// plane strides (elements per plane)
#define PX1  ((size_t)M2 * 256)
#define PH   ((size_t)M2 * 512)
#define PE   ((size_t)M2 * 256)

// ---------------- device scratch ----------------
__device__ float g_x1[(size_t)M2 * 256];
__device__ float g_enc[(size_t)M2 * 256];          // rows 0..M-1 src, M..2M-1 tgt
__device__ float g_u[(size_t)MROWS * 256];

__device__ __half g_x1P  [2 * (size_t)M2 * 256];
__device__ __half g_hP   [2 * (size_t)M2 * 512];
__device__ __half g_encP [2 * (size_t)M2 * 256];
__device__ __half g_combP[(size_t)MROWS * 512];    // hi plane only (answer path)
__device__ __half g_bigP [(size_t)MROWS * 512];    // hi plane only

// fp16 weight planes (2 planes each, scaled by WSCALE)
__device__ __half g_W1P [2 * 256 * 1024];
__device__ __half g_WabP[2 * 1024 * 256];   // interleaved gate/value rows
__device__ __half g_WfP [2 * 256 * 512];
__device__ __half g_WbTP[2 * 256 * 256];
__device__ __half g_Wa1P[2 * 512 * 512];
__device__ __half g_Wa2P[2 * 1024 * 512];

// ---------------- helpers ----------------
__device__ __forceinline__ uint32_t smem_u32(const void* p) {
    uint32_t a;
    asm("{ .reg .u64 t; cvta.to.shared.u64 t, %1; cvt.u32.u64 %0, t; }" : "=r"(a) : "l"(p));
    return a;
}
__device__ __forceinline__ float gelu_tanh(float x) {
    float x3 = x * x * x;
    return 0.5f * x * (1.0f + tanhf(0.7978845608028654f * (x + 0.044715f * x3)));
}
__device__ __forceinline__ void ldsm4(uint32_t& r0, uint32_t& r1, uint32_t& r2, uint32_t& r3,
                                      uint32_t addr) {
    asm volatile("ldmatrix.sync.aligned.m8n8.x4.shared.b16 {%0,%1,%2,%3}, [%4];"
                 : "=r"(r0), "=r"(r1), "=r"(r2), "=r"(r3) : "r"(addr));
}
__device__ __forceinline__ void mma16816(float* c, const uint32_t* a, const uint32_t* b) {
    asm volatile("mma.sync.aligned.m16n8k16.row.col.f32.f16.f16.f32 "
                 "{%0,%1,%2,%3}, {%4,%5,%6,%7}, {%8,%9}, {%0,%1,%2,%3};"
                 : "+f"(c[0]), "+f"(c[1]), "+f"(c[2]), "+f"(c[3])
                 : "r"(a[0]), "r"(a[1]), "r"(a[2]), "r"(a[3]), "r"(b[0]), "r"(b[1]));
}
__device__ __forceinline__ uint32_t packh(float x, float y) {
    __half h0 = __float2half(x), h1 = __float2half(y);
    return (uint32_t)__half_as_ushort(h0) | ((uint32_t)__half_as_ushort(h1) << 16);
}
#define CP_ASYNC16(dst, src) \
    asm volatile("cp.async.cg.shared.global [%0], [%1], 16;" :: "r"(dst), "l"(src) : "memory")
#define CP_COMMIT() asm volatile("cp.async.commit_group;" ::: "memory")
#define CP_WAIT0()  asm volatile("cp.async.wait_group 0;" ::: "memory")
#define CP_WAIT1()  asm volatile("cp.async.wait_group 1;" ::: "memory")

// ---------------- layer1 GEMM: fp32 A, in-kernel split, 2-stage ----------------
#define GBUF 30720
#define SMEM_L1 61440

__global__ __launch_bounds__(256, 2) void gemm_l1(
    const float* __restrict__ Asrc, const float* __restrict__ Atgt,
    const __half* __restrict__ Bp, size_t bPstride,
    const float* __restrict__ bias, float* __restrict__ Cf,
    int N, int K, int Nout)
{
    extern __shared__ char smem[];
    const uint32_t sb = smem_u32(smem);
    const int tid = threadIdx.x, lane = tid & 31, wid = tid >> 5;
    const int bm = blockIdx.y * 128, bn = blockIdx.x * 64;
    const int wm = (wid >> 1) * 32, wn = (wid & 1) * 32;

    const float* A = (bm < MROWS) ? Asrc : (Atgt - (size_t)MROWS * K);

    const uint32_t aLd0 = sb + (uint32_t)((wm + (lane & 15)) * 80 + (lane >> 4) * 16);
    const uint32_t bLd0 = sb + 20480u +
        (uint32_t)(((wn + (lane & 7) + ((lane >> 4) & 1) * 8) * 80) + ((lane >> 3) & 1) * 16);

    float acc[2][4][4];
#pragma unroll
    for (int mt = 0; mt < 2; mt++)
#pragma unroll
        for (int nt = 0; nt < 4; nt++)
#pragma unroll
            for (int i = 0; i < 4; i++) acc[mt][nt][i] = 0.0f;

    const int nkb = K >> 5;

    const int arow = tid >> 1, acol = (tid & 1) * 16;
    const float* aBase = A + (size_t)(bm + arow) * K + acol;
    const uint32_t aStsOff = (uint32_t)(arow * 80 + acol * 2);
    const int brow = tid >> 2, bseg = tid & 3;
    const __half* bBase = Bp + (size_t)(bn + brow) * K + bseg * 8;
    const uint32_t bSts = sb + 20480u + (uint32_t)(brow * 80 + bseg * 16);

    {
        float v[16];
#pragma unroll
        for (int j = 0; j < 4; j++)
            *(float4*)(v + j * 4) = *(const float4*)(aBase + j * 4);
        uint32_t hp[8], lp[8];
#pragma unroll
        for (int j = 0; j < 8; j++) {
            __half h0 = __float2half(v[2 * j]), h1 = __float2half(v[2 * j + 1]);
            hp[j] = (uint32_t)__half_as_ushort(h0) | ((uint32_t)__half_as_ushort(h1) << 16);
            lp[j] = packh(v[2 * j] - __half2float(h0), v[2 * j + 1] - __half2float(h1));
        }
        *(uint4*)(smem + aStsOff)              = *(uint4*)hp;
        *(uint4*)(smem + aStsOff + 16)         = *(uint4*)(hp + 4);
        *(uint4*)(smem + aStsOff + 10240)      = *(uint4*)lp;
        *(uint4*)(smem + aStsOff + 10240 + 16) = *(uint4*)(lp + 4);
#pragma unroll
        for (int pl = 0; pl < 2; pl++)
            CP_ASYNC16(bSts + pl * 5120u, bBase + (size_t)pl * bPstride);
        CP_COMMIT();
        CP_WAIT0();
        __syncthreads();
    }

    for (int kb = 0; kb < nkb; kb++) {
        const uint32_t cur = (uint32_t)(kb & 1) * GBUF;
        const uint32_t nxt = (uint32_t)((kb + 1) & 1) * GBUF;
        const bool has = (kb + 1) < nkb;

        float vstage[16];
        if (has) {
            const float* ap = aBase + (kb + 1) * 32;
#pragma unroll
            for (int j = 0; j < 4; j++)
                *(float4*)(vstage + j * 4) = *(const float4*)(ap + j * 4);
            const __half* bp = bBase + (kb + 1) * 32;
#pragma unroll
            for (int pl = 0; pl < 2; pl++)
                CP_ASYNC16(bSts + nxt + pl * 5120u, bp + (size_t)pl * bPstride);
        }
        CP_COMMIT();

#pragma unroll
        for (int ks = 0; ks < 2; ks++) {
            uint32_t af[2][2][4];
#pragma unroll
            for (int mt = 0; mt < 2; mt++)
#pragma unroll
                for (int pl = 0; pl < 2; pl++)
                    ldsm4(af[mt][pl][0], af[mt][pl][1], af[mt][pl][2], af[mt][pl][3],
                          aLd0 + cur + pl * 10240u + mt * 16 * 80 + ks * 32);
            uint32_t bf[2][4][2];
#pragma unroll
            for (int pl = 0; pl < 2; pl++)
#pragma unroll
                for (int nt2 = 0; nt2 < 2; nt2++) {
                    uint32_t r0, r1, r2, r3;
                    ldsm4(r0, r1, r2, r3,
                          bLd0 + cur + pl * 5120u + nt2 * 16 * 80 + ks * 32);
                    bf[pl][nt2 * 2][0] = r0; bf[pl][nt2 * 2][1] = r1;
                    bf[pl][nt2 * 2 + 1][0] = r2; bf[pl][nt2 * 2 + 1][1] = r3;
                }
#pragma unroll
            for (int prod = 0; prod < 3; prod++) {
                const int apl = (prod == 2) ? 1 : 0;
                const int bpl = (prod == 1) ? 1 : 0;
#pragma unroll
                for (int mt = 0; mt < 2; mt++)
#pragma unroll
                    for (int nt = 0; nt < 4; nt++)
                        mma16816(acc[mt][nt], af[mt][apl], bf[bpl][nt]);
            }
        }

        if (has) {
            uint32_t hp[8], lp[8];
#pragma unroll
            for (int j = 0; j < 8; j++) {
                __half h0 = __float2half(vstage[2 * j]), h1 = __float2half(vstage[2 * j + 1]);
                hp[j] = (uint32_t)__half_as_ushort(h0) | ((uint32_t)__half_as_ushort(h1) << 16);
                lp[j] = packh(vstage[2 * j] - __half2float(h0), vstage[2 * j + 1] - __half2float(h1));
            }
            uint32_t off = aStsOff + nxt;
            *(uint4*)(smem + off)              = *(uint4*)hp;
            *(uint4*)(smem + off + 16)         = *(uint4*)(hp + 4);
            *(uint4*)(smem + off + 10240)      = *(uint4*)lp;
            *(uint4*)(smem + off + 10240 + 16) = *(uint4*)(lp + 4);
        }
        CP_WAIT0();
        __syncthreads();
    }

#pragma unroll
    for (int mt = 0; mt < 2; mt++) {
        int row0 = bm + wm + mt * 16 + (lane >> 2);
#pragma unroll
        for (int nt = 0; nt < 4; nt++) {
            int col0 = bn + wn + nt * 8 + (lane & 3) * 2;
            float b0 = bias[col0], b1 = bias[col0 + 1];
            *(float2*)(Cf + (size_t)row0 * Nout + col0) =
                make_float2(acc[mt][nt][0] * ISCALE + b0, acc[mt][nt][1] * ISCALE + b1);
            *(float2*)(Cf + (size_t)(row0 + 8) * Nout + col0) =
                make_float2(acc[mt][nt][2] * ISCALE + b0, acc[mt][nt][3] * ISCALE + b1);
        }
    }
}

// ---------------- HMMA GEMM (occupancy-optimized, fp16-plane A) ----------------
// NPROD=3: A 2 planes, B 2 planes, hh+hl+lh, 2 stages (smem 61440 -> 3 CTAs/SM).
// NPROD=1: A hi, B hi, hh only, 3 stages (smem 46080 -> 3 CTAs/SM).
// ACT: 0 none, 1 gelu, 2 swiglu. OUTMODE bit0 fp32, bit1 fp16 hi+lo, bit2 fp16 hi,
// bit3: plane outputs only for rows < MROWS.
template <int ACT, int OUTMODE, int NPROD>
__global__ __launch_bounds__(256, 3) void gemm_mma(
    const __half* __restrict__ Ap, size_t aPstride,
    const __half* __restrict__ Bp, size_t bPstride,
    const float* __restrict__ bias,
    float* __restrict__ Cf,
    __half* __restrict__ Cp, size_t cPstride,
    int N, int K, int Nout)
{
    constexpr int A_PL = (NPROD == 3) ? 2 : 1;
    constexpr int B_PL = (NPROD >= 2) ? 2 : 1;
    constexpr uint32_t ASZ = A_PL * 10240u;
    constexpr uint32_t STG_SZ = ASZ + B_PL * 5120u;
    constexpr int NSTG = (NPROD == 1) ? 3 : 2;

    extern __shared__ char smem[];
    const uint32_t sb = smem_u32(smem);
    const int tid = threadIdx.x, lane = tid & 31, wid = tid >> 5;
    const int bm = blockIdx.y * 128, bn = blockIdx.x * 64;
    const int wm = (wid >> 1) * 32, wn = (wid & 1) * 32;

    const uint32_t aLd0 = sb + (uint32_t)((wm + (lane & 15)) * 80 + (lane >> 4) * 16);
    const uint32_t bLd0 = sb + ASZ +
        (uint32_t)(((wn + (lane & 7) + ((lane >> 4) & 1) * 8) * 80) + ((lane >> 3) & 1) * 16);

    float acc[2][4][4];
#pragma unroll
    for (int mt = 0; mt < 2; mt++)
#pragma unroll
        for (int nt = 0; nt < 4; nt++)
#pragma unroll
            for (int i = 0; i < 4; i++) acc[mt][nt][i] = 0.0f;

    const int nkb = K >> 5;

    // rolling source pointers (advance 32 halves per issue) + fixed smem dst offsets
    const __half* aPtr[2 * A_PL];
    uint32_t aDst[2 * A_PL];
#pragma unroll
    for (int t = 0; t < 2 * A_PL; t++) {
        int idx = t * 256 + tid;
        int pl = idx >> 9, row = (idx >> 2) & 127, s = idx & 3;
        aPtr[t] = Ap + (size_t)pl * aPstride + (size_t)(bm + row) * K + s * 8;
        aDst[t] = (uint32_t)(pl * 10240 + row * 80 + s * 16);
    }
    const __half* bPtr[B_PL];
    uint32_t bDst[B_PL];
#pragma unroll
    for (int t = 0; t < B_PL; t++) {
        int idx = t * 256 + tid;
        int pl = idx >> 8, row = (idx >> 2) & 63, s = idx & 3;
        bPtr[t] = Bp + (size_t)pl * bPstride + (size_t)(bn + row) * K + s * 8;
        bDst[t] = ASZ + (uint32_t)(pl * 5120 + row * 80 + s * 16);
    }

    auto issue = [&](uint32_t base) {
#pragma unroll
        for (int t = 0; t < 2 * A_PL; t++) {
            CP_ASYNC16(sb + base + aDst[t], aPtr[t]);
            aPtr[t] += 32;
        }
#pragma unroll
        for (int t = 0; t < B_PL; t++) {
            CP_ASYNC16(sb + base + bDst[t], bPtr[t]);
            bPtr[t] += 32;
        }
    };

    // prologue: stages 0..NSTG-2
    issue(0);
    CP_COMMIT();
#pragma unroll
    for (int s = 1; s < NSTG - 1; s++) {
        if (nkb > s) issue(s * STG_SZ);
        CP_COMMIT();
    }

    uint32_t curStage = 0;
    for (int kb = 0; kb < nkb; kb++) {
        if (NSTG == 2) CP_WAIT0(); else CP_WAIT1();
        __syncthreads();
        const uint32_t cur = curStage * STG_SZ;
        uint32_t nxtStage = curStage + (NSTG - 1);
        if (nxtStage >= NSTG) nxtStage -= NSTG;
        if (kb + NSTG - 1 < nkb) issue(nxtStage * STG_SZ);
        CP_COMMIT();
        curStage = (curStage + 1 == NSTG) ? 0 : curStage + 1;

#pragma unroll
        for (int ks = 0; ks < 2; ks++) {
            uint32_t af[2][A_PL][4];
#pragma unroll
            for (int mt = 0; mt < 2; mt++)
#pragma unroll
                for (int pl = 0; pl < A_PL; pl++)
                    ldsm4(af[mt][pl][0], af[mt][pl][1], af[mt][pl][2], af[mt][pl][3],
                          aLd0 + cur + pl * 10240u + mt * 16 * 80 + ks * 32);
            uint32_t bf[B_PL][4][2];
#pragma unroll
            for (int pl = 0; pl < B_PL; pl++)
#pragma unroll
                for (int nt2 = 0; nt2 < 2; nt2++) {
                    uint32_t r0, r1, r2, r3;
                    ldsm4(r0, r1, r2, r3,
                          bLd0 + cur + pl * 5120u + nt2 * 16 * 80 + ks * 32);
                    bf[pl][nt2 * 2][0] = r0; bf[pl][nt2 * 2][1] = r1;
                    bf[pl][nt2 * 2 + 1][0] = r2; bf[pl][nt2 * 2 + 1][1] = r3;
                }
#pragma unroll
            for (int prod = 0; prod < NPROD; prod++) {
                const int apl = (prod == 2) ? 1 : 0;
                const int bpl = (prod == 1) ? 1 : 0;
#pragma unroll
                for (int mt = 0; mt < 2; mt++)
#pragma unroll
                    for (int nt = 0; nt < 4; nt++)
                        mma16816(acc[mt][nt], af[mt][apl], bf[bpl][nt]);
            }
        }
    }

    // ---- epilogue ----
    if (ACT == 2) {
        __syncthreads();
        float* vs = (float*)smem;
        if (wn == 32) {
#pragma unroll
            for (int mt = 0; mt < 2; mt++)
#pragma unroll
                for (int nt = 0; nt < 4; nt++) {
                    int r0 = wm + mt * 16 + (lane >> 2);
                    int c = nt * 8 + (lane & 3) * 2;
                    vs[r0 * 34 + c]           = acc[mt][nt][0] * ISCALE;
                    vs[r0 * 34 + c + 1]       = acc[mt][nt][1] * ISCALE;
                    vs[(r0 + 8) * 34 + c]     = acc[mt][nt][2] * ISCALE;
                    vs[(r0 + 8) * 34 + c + 1] = acc[mt][nt][3] * ISCALE;
                }
        }
        __syncthreads();
        if (wn == 0) {
#pragma unroll
            for (int mt = 0; mt < 2; mt++) {
                int r0 = wm + mt * 16 + (lane >> 2);
#pragma unroll
                for (int nt = 0; nt < 4; nt++) {
                    int c = nt * 8 + (lane & 3) * 2;
                    float g0 = acc[mt][nt][0] * ISCALE, g1 = acc[mt][nt][1] * ISCALE;
                    float g2 = acc[mt][nt][2] * ISCALE, g3 = acc[mt][nt][3] * ISCALE;
                    float o0 = g0 / (1.0f + expf(-g0)) * vs[r0 * 34 + c];
                    float o1 = g1 / (1.0f + expf(-g1)) * vs[r0 * 34 + c + 1];
                    float o2 = g2 / (1.0f + expf(-g2)) * vs[(r0 + 8) * 34 + c];
                    float o3 = g3 / (1.0f + expf(-g3)) * vs[(r0 + 8) * 34 + c + 1];
                    size_t row = (size_t)(bm + r0);
                    int col = (bn >> 1) + c;
                    __half h0 = __float2half(o0), h1 = __float2half(o1);
                    __half h2 = __float2half(o2), h3 = __float2half(o3);
                    *(uint32_t*)(Cp + row * Nout + col) =
                        (uint32_t)__half_as_ushort(h0) | ((uint32_t)__half_as_ushort(h1) << 16);
                    *(uint32_t*)(Cp + cPstride + row * Nout + col) =
                        packh(o0 - __half2float(h0), o1 - __half2float(h1));
                    *(uint32_t*)(Cp + (row + 8) * Nout + col) =
                        (uint32_t)__half_as_ushort(h2) | ((uint32_t)__half_as_ushort(h3) << 16);
                    *(uint32_t*)(Cp + cPstride + (row + 8) * Nout + col) =
                        packh(o2 - __half2float(h2), o3 - __half2float(h3));
                }
            }
        }
        return;
    }

    const bool doPlanes = !(OUTMODE & 8) || (bm < MROWS);

#pragma unroll
    for (int mt = 0; mt < 2; mt++) {
        int row0 = bm + wm + mt * 16 + (lane >> 2);
#pragma unroll
        for (int nt = 0; nt < 4; nt++) {
            int col0 = bn + wn + nt * 8 + (lane & 3) * 2;
            float b0 = 0.f, b1 = 0.f;
            if (bias) { b0 = bias[col0]; b1 = bias[col0 + 1]; }
            float o0 = acc[mt][nt][0] * ISCALE + b0;
            float o1 = acc[mt][nt][1] * ISCALE + b1;
            float o2 = acc[mt][nt][2] * ISCALE + b0;
            float o3 = acc[mt][nt][3] * ISCALE + b1;
            if (ACT == 1) {
                o0 = gelu_tanh(o0); o1 = gelu_tanh(o1);
                o2 = gelu_tanh(o2); o3 = gelu_tanh(o3);
            }
            if (OUTMODE & 1) {
                *(float2*)(Cf + (size_t)row0 * Nout + col0) = make_float2(o0, o1);
                *(float2*)(Cf + (size_t)(row0 + 8) * Nout + col0) = make_float2(o2, o3);
            }
            if ((OUTMODE & 2) && doPlanes) {
                __half h0 = __float2half(o0), h1 = __float2half(o1);
                __half h2 = __float2half(o2), h3 = __float2half(o3);
                *(uint32_t*)(Cp + (size_t)row0 * Nout + col0) =
                    (uint32_t)__half_as_ushort(h0) | ((uint32_t)__half_as_ushort(h1) << 16);
                *(uint32_t*)(Cp + cPstride + (size_t)row0 * Nout + col0) =
                    packh(o0 - __half2float(h0), o1 - __half2float(h1));
                *(uint32_t*)(Cp + (size_t)(row0 + 8) * Nout + col0) =
                    (uint32_t)__half_as_ushort(h2) | ((uint32_t)__half_as_ushort(h3) << 16);
                *(uint32_t*)(Cp + cPstride + (size_t)(row0 + 8) * Nout + col0) =
                    packh(o2 - __half2float(h2), o3 - __half2float(h3));
            }
            if (OUTMODE & 4) {
                *(uint32_t*)(Cp + (size_t)row0 * Nout + col0) = packh(o0, o1);
                *(uint32_t*)(Cp + (size_t)(row0 + 8) * Nout + col0) = packh(o2, o3);
            }
        }
    }
}

// ---------------- merged weight prep (single launch, region dispatch) ----------------
__global__ void prep_kernel(
    const float* __restrict__ W1, const float* __restrict__ Wa,
    const float* __restrict__ Wb, const float* __restrict__ W2,
    const float* __restrict__ Wc, const float* __restrict__ Wbil,
    const float* __restrict__ Wa1, const float* __restrict__ Wa2,
    __half* __restrict__ W1P, __half* __restrict__ WabP,
    __half* __restrict__ WfP, __half* __restrict__ WbTP,
    __half* __restrict__ Wa1P, __half* __restrict__ Wa2P)
{
    int i = blockIdx.x * 256 + threadIdx.x;
    float w;
    __half* out;
    int pstride, local;

    if (i < 262144) {
        local = i; w = W1[local]; out = W1P; pstride = 262144;
    } else if (i < 524288) {
        local = i - 262144;
        int nrow = local >> 8, k = local & 255;
        int j = nrow >> 6, r = nrow & 63;
        w = (r < 32) ? Wa[(j * 32 + r) * 256 + k] : Wb[(j * 32 + r - 32) * 256 + k];
        out = WabP; pstride = 262144;
    } else if (i < 655360) {
        local = i - 524288;
        int r = local >> 9, c = local & 511;
        float s = 0.0f;
        for (int k = 0; k < 256; k++) s += W2[r * 256 + k] * Wc[k * 512 + c];
        w = s; out = WfP; pstride = 131072;
    } else if (i < 720896) {
        local = i - 655360;
        int nrow = local >> 8, k = local & 255;
        w = Wbil[k * 256 + nrow];
        out = WbTP; pstride = 65536;
    } else if (i < 983040) {
        local = i - 720896; w = Wa1[local]; out = Wa1P; pstride = 262144;
    } else {
        local = i - 983040; w = Wa2[local]; out = Wa2P; pstride = 524288;
    }

    float r = w * WSCALE;
    __half h = __float2half(r);
    out[local] = h;
    r -= __half2float(h);
    out[(size_t)pstride + local] = __float2half(r);
}

// ---------------- elementwise ----------------
template <int NC>
__global__ void rmsnorm_kernel(float* __restrict__ x, const float* __restrict__ g, int rows)
{
    int row = blockIdx.x * 8 + (threadIdx.x >> 5);
    int lane = threadIdx.x & 31;
    if (row >= rows) return;
    float* p = x + (size_t)row * NC;
    constexpr int V = NC / 32;
    float v[V];
    float ss = 0.0f;
#pragma unroll
    for (int i = 0; i < V; i++) { v[i] = p[lane + 32 * i]; ss += v[i] * v[i]; }
#pragma unroll
    for (int o = 16; o > 0; o >>= 1) ss += __shfl_xor_sync(0xffffffffu, ss, o);
    float sc = rsqrtf(ss * (1.0f / NC) + 1e-6f);
#pragma unroll
    for (int i = 0; i < V; i++) p[lane + 32 * i] = v[i] * sc * g[lane + 32 * i];
}

__global__ void rmsnorm_planes(const float* __restrict__ x, const float* __restrict__ g,
                               __half* __restrict__ out, int rows)
{
    int row = blockIdx.x * 8 + (threadIdx.x >> 5);
    int lane = threadIdx.x & 31;
    if (row >= rows) return;
    const float* p = x + (size_t)row * 256;
    float v[8];
    float ss = 0.0f;
#pragma unroll
    for (int i = 0; i < 8; i++) { v[i] = p[lane + 32 * i]; ss += v[i] * v[i]; }
#pragma unroll
    for (int o = 16; o > 0; o >>= 1) ss += __shfl_xor_sync(0xffffffffu, ss, o);
    float sc = rsqrtf(ss * (1.0f / 256.0f) + 1e-6f);
#pragma unroll
    for (int i = 0; i < 8; i++) {
        float o = v[i] * sc * g[lane + 32 * i];
        __half h = __float2half(o);
        out[(size_t)row * 256 + lane + 32 * i] = h;
        out[PX1 + (size_t)row * 256 + lane + 32 * i] = __float2half(o - __half2float(h));
    }
}

// ---------------- per-batch sinkhorn etc ----------------
__global__ __launch_bounds__(256) void batch_kernel(
    const float* __restrict__ u, const float* __restrict__ tgt,
    const float* __restrict__ src, const float* __restrict__ bbil,
    const float* __restrict__ Wc1, const float* __restrict__ bc1,
    float* __restrict__ out_mapping, float* __restrict__ out_mapped,
    float* __restrict__ out_conf, __half* __restrict__ combP)
{
    const int b = blockIdx.x;
    const int tid = threadIdx.x;
    __shared__ float u_s[RROLE * HDIM];
    __shared__ float t_s[RROLE * HDIM];
    __shared__ float s_s[RROLE * HDIM];
    __shared__ float la[RROLE * RROLE];
    __shared__ float map_s[RROLE * RROLE];
    __shared__ float lse[RROLE];
    __shared__ float red[256];

    const size_t base = (size_t)b * RROLE * HDIM;
    for (int e = tid; e < RROLE * HDIM; e += 256) {
        u_s[e] = u[base + e];
        t_s[e] = tgt[base + e];
        s_s[e] = src[base + e];
    }
    __syncthreads();

    const float bb = bbil[0];
    const int warp = tid >> 5, lane = tid & 31;
    for (int p = warp; p < RROLE * RROLE; p += 8) {
        int i = p / RROLE, j = p % RROLE;
        float d = 0.0f;
        for (int h = lane; h < HDIM; h += 32) d += u_s[i * HDIM + h] * t_s[j * HDIM + h];
#pragma unroll
        for (int o = 16; o > 0; o >>= 1) d += __shfl_xor_sync(0xffffffffu, d, o);
        if (lane == 0) la[p] = (d + bb) * TEMP_INV;
    }
    __syncthreads();

    for (int it = 0; it < SINKHORN_ITERS; it++) {
        if (tid < RROLE) {
            float m = -1e30f;
            for (int j = 0; j < RROLE; j++) m = fmaxf(m, la[tid * RROLE + j]);
            float s = 0.0f;
            for (int j = 0; j < RROLE; j++) s += expf(la[tid * RROLE + j] - m);
            lse[tid] = m + logf(s);
        }
        __syncthreads();
        if (tid < RROLE * RROLE) la[tid] -= lse[tid / RROLE];
        __syncthreads();
        if (tid < RROLE) {
            float m = -1e30f;
            for (int i = 0; i < RROLE; i++) m = fmaxf(m, la[i * RROLE + tid]);
            float s = 0.0f;
            for (int i = 0; i < RROLE; i++) s += expf(la[i * RROLE + tid] - m);
            lse[tid] = m + logf(s);
        }
        __syncthreads();
        if (tid < RROLE * RROLE) la[tid] -= lse[tid % RROLE];
        __syncthreads();
    }

    if (tid < RROLE * RROLE) {
        float mv = expf(la[tid]);
        map_s[tid] = mv;
        out_mapping[(size_t)b * RROLE * RROLE + tid] = mv;
    }
    __syncthreads();

    float local = 0.0f;
    for (int e = tid; e < RROLE * HDIM; e += 256) {
        int i = e >> 8;
        int h = e & 255;
        float v = 0.0f;
#pragma unroll
        for (int j = 0; j < RROLE; j++) v += map_s[i * RROLE + j] * t_s[j * HDIM + h];
        out_mapped[base + e] = v;
        size_t cbase = ((size_t)b * RROLE + i) * 512;
        combP[cbase + h] = __float2half(v);
        combP[cbase + 256 + h] = __float2half(t_s[i * HDIM + h]);
        local += fabsf(v - s_s[e]);
    }
    red[tid] = local;
    __syncthreads();
    for (int s = 128; s > 0; s >>= 1) {
        if (tid < s) red[tid] += red[tid + s];
        __syncthreads();
    }
    if (tid == 0) {
        float conf_in = red[0] * (1.0f / (RROLE * HDIM));
        float z = conf_in * Wc1[0] + bc1[0];
        out_conf[b] = 1.0f / (1.0f + expf(-z));
    }
}

// ---------------- launch ----------------
#define SMEM3 61440
#define SMEM1 46080

extern "C" void kernel_launch(void* const* d_in, const int* in_sizes, int n_in,
                              void* d_out, int out_size)
{
    (void)in_sizes; (void)n_in; (void)out_size;
    const float* src  = (const float*)d_in[0];
    const float* tgt  = (const float*)d_in[1];
    const float* W1   = (const float*)d_in[2];
    const float* b1   = (const float*)d_in[3];
    const float* g1   = (const float*)d_in[4];
    const float* Wa   = (const float*)d_in[5];
    const float* Wb   = (const float*)d_in[6];
    const float* Wc   = (const float*)d_in[7];
    const float* W2   = (const float*)d_in[8];
    const float* b2   = (const float*)d_in[9];
    const float* Wbil = (const float*)d_in[10];
    const float* bbil = (const float*)d_in[11];
    const float* Wa1  = (const float*)d_in[12];
    const float* ba1  = (const float*)d_in[13];
    const float* Wa2  = (const float*)d_in[14];
    const float* ba2  = (const float*)d_in[15];
    const float* g2   = (const float*)d_in[16];
    const float* Wc1  = (const float*)d_in[17];
    const float* bc1  = (const float*)d_in[18];
    float* out = (float*)d_out;

    float *x1, *enc, *ub;
    __half *x1P, *hP, *encP, *combP, *bigP;
    __half *W1P, *WabP, *WfP, *WbTP, *Wa1P, *Wa2P;
    cudaGetSymbolAddress((void**)&x1,    g_x1);
    cudaGetSymbolAddress((void**)&enc,   g_enc);
    cudaGetSymbolAddress((void**)&ub,    g_u);
    cudaGetSymbolAddress((void**)&x1P,   g_x1P);
    cudaGetSymbolAddress((void**)&hP,    g_hP);
    cudaGetSymbolAddress((void**)&encP,  g_encP);
    cudaGetSymbolAddress((void**)&combP, g_combP);
    cudaGetSymbolAddress((void**)&bigP,  g_bigP);
    cudaGetSymbolAddress((void**)&W1P,   g_W1P);
    cudaGetSymbolAddress((void**)&WabP,  g_WabP);
    cudaGetSymbolAddress((void**)&WfP,   g_WfP);
    cudaGetSymbolAddress((void**)&WbTP,  g_WbTP);
    cudaGetSymbolAddress((void**)&Wa1P,  g_Wa1P);
    cudaGetSymbolAddress((void**)&Wa2P,  g_Wa2P);

    cudaFuncSetAttribute(gemm_l1, cudaFuncAttributeMaxDynamicSharedMemorySize, SMEM_L1);
    cudaFuncSetAttribute(gemm_mma<0,11,3>, cudaFuncAttributeMaxDynamicSharedMemorySize, SMEM3);
    cudaFuncSetAttribute(gemm_mma<0,1,3>, cudaFuncAttributeMaxDynamicSharedMemorySize, SMEM3);
    cudaFuncSetAttribute(gemm_mma<2,2,3>, cudaFuncAttributeMaxDynamicSharedMemorySize, SMEM3);
    cudaFuncSetAttribute(gemm_mma<1,4,1>, cudaFuncAttributeMaxDynamicSharedMemorySize, SMEM1);
    cudaFuncSetAttribute(gemm_mma<0,1,1>, cudaFuncAttributeMaxDynamicSharedMemorySize, SMEM1);

    // ---- merged weight prep (single launch; 1,507,328 elements) ----
    prep_kernel<<<5888, 256>>>(W1, Wa, Wb, W2, Wc, Wbil, Wa1, Wa2,
                               W1P, WabP, WfP, WbTP, Wa1P, Wa2P);

    // ---- merged encoder (src rows 0..M-1, tgt rows M..2M-1) ----
    gemm_l1<<<dim3(4, M2 / 128), 256, SMEM_L1>>>(
        src, tgt, W1P, 262144, b1, x1, 256, 1024, 256);
    rmsnorm_planes<<<M2 / 8, 256>>>(x1, g1, x1P, M2);
    gemm_mma<2,2,3><<<dim3(16, M2 / 128), 256, SMEM3>>>(
        x1P, PX1, WabP, 262144, nullptr, nullptr, hP, PH, 1024, 256, 512);
    gemm_mma<0,11,3><<<dim3(4, M2 / 128), 256, SMEM3>>>(
        hP, PH, WfP, 131072, b2, enc, encP, PE, 256, 512, 256);

    // ---- bilinear u = enc_src @ Wbil (first MROWS rows of encP) ----
    gemm_mma<0,1,3><<<dim3(4, MROWS / 128), 256, SMEM3>>>(
        encP, PE, WbTP, 65536, nullptr, ub, nullptr, 0, 256, 256, 256);

    // ---- sinkhorn / mapping / confidence / combined (hi plane only) ----
    batch_kernel<<<BATCH, 256>>>(ub, enc + (size_t)MROWS * 256, enc, bbil, Wc1, bc1,
                                 out + OUT_MAPPING_OFF, out + OUT_MAPPED_OFF,
                                 out + OUT_CONF_OFF, combP);

    // ---- answer projection (1-product path: hi x hi only, 3-stage) ----
    gemm_mma<1,4,1><<<dim3(8, MROWS / 128), 256, SMEM1>>>(
        combP, 0, Wa1P, 262144, ba1, nullptr, bigP, 0, 512, 512, 512);
    gemm_mma<0,1,1><<<dim3(16, MROWS / 128), 256, SMEM1>>>(
        bigP, 0, Wa2P, 524288, ba2, out + OUT_ANSWER_OFF, nullptr, 0, 1024, 512, 1024);
    rmsnorm_kernel<DDIM><<<MROWS / 8, 256>>>(out + OUT_ANSWER_OFF, g2, MROWS);
}

// round 16
// speedup vs baseline: 1.0946x; 1.0119x over previous
#include <cuda_runtime.h>
#include <cuda_fp16.h>
#include <cstdint>
#include <math.h>

#define BATCH 8192
#define RROLE 6
#define DDIM 1024
#define HDIM 256
#define MROWS (BATCH * RROLE)          // 49152
#define M2 (2 * MROWS)                 // 98304 (src+tgt merged)
#define TEMP_INV 2.0f
#define SINKHORN_ITERS 5

#define OUT_ANSWER_OFF  0
#define OUT_MAPPING_OFF ((size_t)MROWS * DDIM)
#define OUT_MAPPED_OFF  (OUT_MAPPING_OFF + (size_t)BATCH * RROLE * RROLE)
#define OUT_CONF_OFF    (OUT_MAPPED_OFF + (size_t)MROWS * HDIM)

#define WSCALE 1024.0f
#define ISCALE (1.0f / 1024.0f)

// plane strides (elements per plane)
#define PX1  ((size_t)M2 * 256)
#define PH   ((size_t)M2 * 512)
#define PE   ((size_t)M2 * 256)

// ---------------- device scratch ----------------
__device__ float g_x1[(size_t)M2 * 256];
__device__ float g_enc[(size_t)M2 * 256];          // rows 0..M-1 src, M..2M-1 tgt
__device__ float g_u[(size_t)MROWS * 256];

__device__ __half g_x1P  [2 * (size_t)M2 * 256];
__device__ __half g_hP   [2 * (size_t)M2 * 512];
__device__ __half g_encP [2 * (size_t)M2 * 256];
__device__ __half g_combP[(size_t)MROWS * 512];    // hi plane only (answer path)
__device__ __half g_bigP [(size_t)MROWS * 512];    // hi plane only

// fp16 weight planes (2 planes each, scaled by WSCALE)
__device__ __half g_W1P [2 * 256 * 1024];
__device__ __half g_WabP[2 * 1024 * 256];   // interleaved gate/value rows
__device__ __half g_WfP [2 * 256 * 512];
__device__ __half g_WbTP[2 * 256 * 256];
__device__ __half g_Wa1P[2 * 512 * 512];
__device__ __half g_Wa2P[2 * 1024 * 512];

// ---------------- helpers ----------------
__device__ __forceinline__ uint32_t smem_u32(const void* p) {
    uint32_t a;
    asm("{ .reg .u64 t; cvta.to.shared.u64 t, %1; cvt.u32.u64 %0, t; }" : "=r"(a) : "l"(p));
    return a;
}
__device__ __forceinline__ float gelu_tanh(float x) {
    float x3 = x * x * x;
    return 0.5f * x * (1.0f + tanhf(0.7978845608028654f * (x + 0.044715f * x3)));
}
__device__ __forceinline__ void ldsm4(uint32_t& r0, uint32_t& r1, uint32_t& r2, uint32_t& r3,
                                      uint32_t addr) {
    asm volatile("ldmatrix.sync.aligned.m8n8.x4.shared.b16 {%0,%1,%2,%3}, [%4];"
                 : "=r"(r0), "=r"(r1), "=r"(r2), "=r"(r3) : "r"(addr));
}
__device__ __forceinline__ void mma16816(float* c, const uint32_t* a, const uint32_t* b) {
    asm volatile("mma.sync.aligned.m16n8k16.row.col.f32.f16.f16.f32 "
                 "{%0,%1,%2,%3}, {%4,%5,%6,%7}, {%8,%9}, {%0,%1,%2,%3};"
                 : "+f"(c[0]), "+f"(c[1]), "+f"(c[2]), "+f"(c[3])
                 : "r"(a[0]), "r"(a[1]), "r"(a[2]), "r"(a[3]), "r"(b[0]), "r"(b[1]));
}
__device__ __forceinline__ uint32_t packh(float x, float y) {
    __half h0 = __float2half(x), h1 = __float2half(y);
    return (uint32_t)__half_as_ushort(h0) | ((uint32_t)__half_as_ushort(h1) << 16);
}
#define CP_ASYNC16(dst, src) \
    asm volatile("cp.async.cg.shared.global [%0], [%1], 16;" :: "r"(dst), "l"(src) : "memory")
#define CP_COMMIT() asm volatile("cp.async.commit_group;" ::: "memory")
#define CP_WAIT0()  asm volatile("cp.async.wait_group 0;" ::: "memory")
#define CP_WAIT1()  asm volatile("cp.async.wait_group 1;" ::: "memory")

// ---------------- layer1 GEMM: fp32 A, in-kernel split, 2-stage ----------------
#define GBUF 30720
#define SMEM_L1 61440

__global__ __launch_bounds__(256, 3) void gemm_l1(
    const float* __restrict__ Asrc, const float* __restrict__ Atgt,
    const __half* __restrict__ Bp, size_t bPstride,
    const float* __restrict__ bias, float* __restrict__ Cf,
    int N, int K, int Nout)
{
    extern __shared__ char smem[];
    const uint32_t sb = smem_u32(smem);
    const int tid = threadIdx.x, lane = tid & 31, wid = tid >> 5;
    const int bm = blockIdx.y * 128, bn = blockIdx.x * 64;
    const int wm = (wid >> 1) * 32, wn = (wid & 1) * 32;

    const float* A = (bm < MROWS) ? Asrc : (Atgt - (size_t)MROWS * K);

    const uint32_t aLd0 = sb + (uint32_t)((wm + (lane & 15)) * 80 + (lane >> 4) * 16);
    const uint32_t bLd0 = sb + 20480u +
        (uint32_t)(((wn + (lane & 7) + ((lane >> 4) & 1) * 8) * 80) + ((lane >> 3) & 1) * 16);

    float acc[2][4][4];
#pragma unroll
    for (int mt = 0; mt < 2; mt++)
#pragma unroll
        for (int nt = 0; nt < 4; nt++)
#pragma unroll
            for (int i = 0; i < 4; i++) acc[mt][nt][i] = 0.0f;

    const int nkb = K >> 5;

    const int arow = tid >> 1, acol = (tid & 1) * 16;
    const float* aBase = A + (size_t)(bm + arow) * K + acol;
    const uint32_t aStsOff = (uint32_t)(arow * 80 + acol * 2);
    const int brow = tid >> 2, bseg = tid & 3;
    const __half* bBase = Bp + (size_t)(bn + brow) * K + bseg * 8;
    const uint32_t bSts = sb + 20480u + (uint32_t)(brow * 80 + bseg * 16);

    {
        float v[16];
#pragma unroll
        for (int j = 0; j < 4; j++)
            *(float4*)(v + j * 4) = *(const float4*)(aBase + j * 4);
        uint32_t hp[8], lp[8];
#pragma unroll
        for (int j = 0; j < 8; j++) {
            __half h0 = __float2half(v[2 * j]), h1 = __float2half(v[2 * j + 1]);
            hp[j] = (uint32_t)__half_as_ushort(h0) | ((uint32_t)__half_as_ushort(h1) << 16);
            lp[j] = packh(v[2 * j] - __half2float(h0), v[2 * j + 1] - __half2float(h1));
        }
        *(uint4*)(smem + aStsOff)              = *(uint4*)hp;
        *(uint4*)(smem + aStsOff + 16)         = *(uint4*)(hp + 4);
        *(uint4*)(smem + aStsOff + 10240)      = *(uint4*)lp;
        *(uint4*)(smem + aStsOff + 10240 + 16) = *(uint4*)(lp + 4);
#pragma unroll
        for (int pl = 0; pl < 2; pl++)
            CP_ASYNC16(bSts + pl * 5120u, bBase + (size_t)pl * bPstride);
        CP_COMMIT();
        CP_WAIT0();
        __syncthreads();
    }

    for (int kb = 0; kb < nkb; kb++) {
        const uint32_t cur = (uint32_t)(kb & 1) * GBUF;
        const uint32_t nxt = (uint32_t)((kb + 1) & 1) * GBUF;
        const bool has = (kb + 1) < nkb;

        float vstage[16];
        if (has) {
            const float* ap = aBase + (kb + 1) * 32;
#pragma unroll
            for (int j = 0; j < 4; j++)
                *(float4*)(vstage + j * 4) = *(const float4*)(ap + j * 4);
            const __half* bp = bBase + (kb + 1) * 32;
#pragma unroll
            for (int pl = 0; pl < 2; pl++)
                CP_ASYNC16(bSts + nxt + pl * 5120u, bp + (size_t)pl * bPstride);
        }
        CP_COMMIT();

#pragma unroll
        for (int ks = 0; ks < 2; ks++) {
            uint32_t af[2][2][4];
#pragma unroll
            for (int mt = 0; mt < 2; mt++)
#pragma unroll
                for (int pl = 0; pl < 2; pl++)
                    ldsm4(af[mt][pl][0], af[mt][pl][1], af[mt][pl][2], af[mt][pl][3],
                          aLd0 + cur + pl * 10240u + mt * 16 * 80 + ks * 32);
            uint32_t bf[2][4][2];
#pragma unroll
            for (int pl = 0; pl < 2; pl++)
#pragma unroll
                for (int nt2 = 0; nt2 < 2; nt2++) {
                    uint32_t r0, r1, r2, r3;
                    ldsm4(r0, r1, r2, r3,
                          bLd0 + cur + pl * 5120u + nt2 * 16 * 80 + ks * 32);
                    bf[pl][nt2 * 2][0] = r0; bf[pl][nt2 * 2][1] = r1;
                    bf[pl][nt2 * 2 + 1][0] = r2; bf[pl][nt2 * 2 + 1][1] = r3;
                }
#pragma unroll
            for (int prod = 0; prod < 3; prod++) {
                const int apl = (prod == 2) ? 1 : 0;
                const int bpl = (prod == 1) ? 1 : 0;
#pragma unroll
                for (int mt = 0; mt < 2; mt++)
#pragma unroll
                    for (int nt = 0; nt < 4; nt++)
                        mma16816(acc[mt][nt], af[mt][apl], bf[bpl][nt]);
            }
        }

        if (has) {
            uint32_t hp[8], lp[8];
#pragma unroll
            for (int j = 0; j < 8; j++) {
                __half h0 = __float2half(vstage[2 * j]), h1 = __float2half(vstage[2 * j + 1]);
                hp[j] = (uint32_t)__half_as_ushort(h0) | ((uint32_t)__half_as_ushort(h1) << 16);
                lp[j] = packh(vstage[2 * j] - __half2float(h0), vstage[2 * j + 1] - __half2float(h1));
            }
            uint32_t off = aStsOff + nxt;
            *(uint4*)(smem + off)              = *(uint4*)hp;
            *(uint4*)(smem + off + 16)         = *(uint4*)(hp + 4);
            *(uint4*)(smem + off + 10240)      = *(uint4*)lp;
            *(uint4*)(smem + off + 10240 + 16) = *(uint4*)(lp + 4);
        }
        CP_WAIT0();
        __syncthreads();
    }

#pragma unroll
    for (int mt = 0; mt < 2; mt++) {
        int row0 = bm + wm + mt * 16 + (lane >> 2);
#pragma unroll
        for (int nt = 0; nt < 4; nt++) {
            int col0 = bn + wn + nt * 8 + (lane & 3) * 2;
            float b0 = bias[col0], b1 = bias[col0 + 1];
            *(float2*)(Cf + (size_t)row0 * Nout + col0) =
                make_float2(acc[mt][nt][0] * ISCALE + b0, acc[mt][nt][1] * ISCALE + b1);
            *(float2*)(Cf + (size_t)(row0 + 8) * Nout + col0) =
                make_float2(acc[mt][nt][2] * ISCALE + b0, acc[mt][nt][3] * ISCALE + b1);
        }
    }
}

// ---------------- HMMA GEMM (occupancy-optimized, fp16-plane A) ----------------
// NPROD=3: 2 stages, 3 CTAs/SM. NPROD=1: 3 stages, 4 CTAs/SM.
// ACT: 0 none, 1 gelu, 2 swiglu. OUTMODE bit0 fp32, bit1 fp16 hi+lo, bit2 fp16 hi,
// bit3: plane outputs only for rows < MROWS.
template <int ACT, int OUTMODE, int NPROD>
__global__ __launch_bounds__(256, (NPROD == 1) ? 4 : 3) void gemm_mma(
    const __half* __restrict__ Ap, size_t aPstride,
    const __half* __restrict__ Bp, size_t bPstride,
    const float* __restrict__ bias,
    float* __restrict__ Cf,
    __half* __restrict__ Cp, size_t cPstride,
    int N, int K, int Nout)
{
    constexpr int A_PL = (NPROD == 3) ? 2 : 1;
    constexpr int B_PL = (NPROD >= 2) ? 2 : 1;
    constexpr uint32_t ASZ = A_PL * 10240u;
    constexpr uint32_t STG_SZ = ASZ + B_PL * 5120u;
    constexpr int NSTG = (NPROD == 1) ? 3 : 2;

    extern __shared__ char smem[];
    const uint32_t sb = smem_u32(smem);
    const int tid = threadIdx.x, lane = tid & 31, wid = tid >> 5;
    const int bm = blockIdx.y * 128, bn = blockIdx.x * 64;
    const int wm = (wid >> 1) * 32, wn = (wid & 1) * 32;

    const uint32_t aLd0 = sb + (uint32_t)((wm + (lane & 15)) * 80 + (lane >> 4) * 16);
    const uint32_t bLd0 = sb + ASZ +
        (uint32_t)(((wn + (lane & 7) + ((lane >> 4) & 1) * 8) * 80) + ((lane >> 3) & 1) * 16);

    float acc[2][4][4];
#pragma unroll
    for (int mt = 0; mt < 2; mt++)
#pragma unroll
        for (int nt = 0; nt < 4; nt++)
#pragma unroll
            for (int i = 0; i < 4; i++) acc[mt][nt][i] = 0.0f;

    const int nkb = K >> 5;

    // rolling source pointers (advance 32 halves per issue) + fixed smem dst offsets
    const __half* aPtr[2 * A_PL];
    uint32_t aDst[2 * A_PL];
#pragma unroll
    for (int t = 0; t < 2 * A_PL; t++) {
        int idx = t * 256 + tid;
        int pl = idx >> 9, row = (idx >> 2) & 127, s = idx & 3;
        aPtr[t] = Ap + (size_t)pl * aPstride + (size_t)(bm + row) * K + s * 8;
        aDst[t] = (uint32_t)(pl * 10240 + row * 80 + s * 16);
    }
    const __half* bPtr[B_PL];
    uint32_t bDst[B_PL];
#pragma unroll
    for (int t = 0; t < B_PL; t++) {
        int idx = t * 256 + tid;
        int pl = idx >> 8, row = (idx >> 2) & 63, s = idx & 3;
        bPtr[t] = Bp + (size_t)pl * bPstride + (size_t)(bn + row) * K + s * 8;
        bDst[t] = ASZ + (uint32_t)(pl * 5120 + row * 80 + s * 16);
    }

    auto issue = [&](uint32_t base) {
#pragma unroll
        for (int t = 0; t < 2 * A_PL; t++) {
            CP_ASYNC16(sb + base + aDst[t], aPtr[t]);
            aPtr[t] += 32;
        }
#pragma unroll
        for (int t = 0; t < B_PL; t++) {
            CP_ASYNC16(sb + base + bDst[t], bPtr[t]);
            bPtr[t] += 32;
        }
    };

    issue(0);
    CP_COMMIT();
#pragma unroll
    for (int s = 1; s < NSTG - 1; s++) {
        if (nkb > s) issue(s * STG_SZ);
        CP_COMMIT();
    }

    uint32_t curStage = 0;
    for (int kb = 0; kb < nkb; kb++) {
        if (NSTG == 2) CP_WAIT0(); else CP_WAIT1();
        __syncthreads();
        const uint32_t cur = curStage * STG_SZ;
        uint32_t nxtStage = curStage + (NSTG - 1);
        if (nxtStage >= NSTG) nxtStage -= NSTG;
        if (kb + NSTG - 1 < nkb) issue(nxtStage * STG_SZ);
        CP_COMMIT();
        curStage = (curStage + 1 == NSTG) ? 0 : curStage + 1;

#pragma unroll
        for (int ks = 0; ks < 2; ks++) {
            uint32_t af[2][A_PL][4];
#pragma unroll
            for (int mt = 0; mt < 2; mt++)
#pragma unroll
                for (int pl = 0; pl < A_PL; pl++)
                    ldsm4(af[mt][pl][0], af[mt][pl][1], af[mt][pl][2], af[mt][pl][3],
                          aLd0 + cur + pl * 10240u + mt * 16 * 80 + ks * 32);
            uint32_t bf[B_PL][4][2];
#pragma unroll
            for (int pl = 0; pl < B_PL; pl++)
#pragma unroll
                for (int nt2 = 0; nt2 < 2; nt2++) {
                    uint32_t r0, r1, r2, r3;
                    ldsm4(r0, r1, r2, r3,
                          bLd0 + cur + pl * 5120u + nt2 * 16 * 80 + ks * 32);
                    bf[pl][nt2 * 2][0] = r0; bf[pl][nt2 * 2][1] = r1;
                    bf[pl][nt2 * 2 + 1][0] = r2; bf[pl][nt2 * 2 + 1][1] = r3;
                }
#pragma unroll
            for (int prod = 0; prod < NPROD; prod++) {
                const int apl = (prod == 2) ? 1 : 0;
                const int bpl = (prod == 1) ? 1 : 0;
#pragma unroll
                for (int mt = 0; mt < 2; mt++)
#pragma unroll
                    for (int nt = 0; nt < 4; nt++)
                        mma16816(acc[mt][nt], af[mt][apl], bf[bpl][nt]);
            }
        }
    }

    // ---- epilogue ----
    if (ACT == 2) {
        __syncthreads();
        float* vs = (float*)smem;
        if (wn == 32) {
#pragma unroll
            for (int mt = 0; mt < 2; mt++)
#pragma unroll
                for (int nt = 0; nt < 4; nt++) {
                    int r0 = wm + mt * 16 + (lane >> 2);
                    int c = nt * 8 + (lane & 3) * 2;
                    vs[r0 * 34 + c]           = acc[mt][nt][0] * ISCALE;
                    vs[r0 * 34 + c + 1]       = acc[mt][nt][1] * ISCALE;
                    vs[(r0 + 8) * 34 + c]     = acc[mt][nt][2] * ISCALE;
                    vs[(r0 + 8) * 34 + c + 1] = acc[mt][nt][3] * ISCALE;
                }
        }
        __syncthreads();
        if (wn == 0) {
#pragma unroll
            for (int mt = 0; mt < 2; mt++) {
                int r0 = wm + mt * 16 + (lane >> 2);
#pragma unroll
                for (int nt = 0; nt < 4; nt++) {
                    int c = nt * 8 + (lane & 3) * 2;
                    float g0 = acc[mt][nt][0] * ISCALE, g1 = acc[mt][nt][1] * ISCALE;
                    float g2 = acc[mt][nt][2] * ISCALE, g3 = acc[mt][nt][3] * ISCALE;
                    float o0 = g0 / (1.0f + expf(-g0)) * vs[r0 * 34 + c];
                    float o1 = g1 / (1.0f + expf(-g1)) * vs[r0 * 34 + c + 1];
                    float o2 = g2 / (1.0f + expf(-g2)) * vs[(r0 + 8) * 34 + c];
                    float o3 = g3 / (1.0f + expf(-g3)) * vs[(r0 + 8) * 34 + c + 1];
                    size_t row = (size_t)(bm + r0);
                    int col = (bn >> 1) + c;
                    __half h0 = __float2half(o0), h1 = __float2half(o1);
                    __half h2 = __float2half(o2), h3 = __float2half(o3);
                    *(uint32_t*)(Cp + row * Nout + col) =
                        (uint32_t)__half_as_ushort(h0) | ((uint32_t)__half_as_ushort(h1) << 16);
                    *(uint32_t*)(Cp + cPstride + row * Nout + col) =
                        packh(o0 - __half2float(h0), o1 - __half2float(h1));
                    *(uint32_t*)(Cp + (row + 8) * Nout + col) =
                        (uint32_t)__half_as_ushort(h2) | ((uint32_t)__half_as_ushort(h3) << 16);
                    *(uint32_t*)(Cp + cPstride + (row + 8) * Nout + col) =
                        packh(o2 - __half2float(h2), o3 - __half2float(h3));
                }
            }
        }
        return;
    }

    const bool doPlanes = !(OUTMODE & 8) || (bm < MROWS);

#pragma unroll
    for (int mt = 0; mt < 2; mt++) {
        int row0 = bm + wm + mt * 16 + (lane >> 2);
#pragma unroll
        for (int nt = 0; nt < 4; nt++) {
            int col0 = bn + wn + nt * 8 + (lane & 3) * 2;
            float b0 = 0.f, b1 = 0.f;
            if (bias) { b0 = bias[col0]; b1 = bias[col0 + 1]; }
            float o0 = acc[mt][nt][0] * ISCALE + b0;
            float o1 = acc[mt][nt][1] * ISCALE + b1;
            float o2 = acc[mt][nt][2] * ISCALE + b0;
            float o3 = acc[mt][nt][3] * ISCALE + b1;
            if (ACT == 1) {
                o0 = gelu_tanh(o0); o1 = gelu_tanh(o1);
                o2 = gelu_tanh(o2); o3 = gelu_tanh(o3);
            }
            if (OUTMODE & 1) {
                *(float2*)(Cf + (size_t)row0 * Nout + col0) = make_float2(o0, o1);
                *(float2*)(Cf + (size_t)(row0 + 8) * Nout + col0) = make_float2(o2, o3);
            }
            if ((OUTMODE & 2) && doPlanes) {
                __half h0 = __float2half(o0), h1 = __float2half(o1);
                __half h2 = __float2half(o2), h3 = __float2half(o3);
                *(uint32_t*)(Cp + (size_t)row0 * Nout + col0) =
                    (uint32_t)__half_as_ushort(h0) | ((uint32_t)__half_as_ushort(h1) << 16);
                *(uint32_t*)(Cp + cPstride + (size_t)row0 * Nout + col0) =
                    packh(o0 - __half2float(h0), o1 - __half2float(h1));
                *(uint32_t*)(Cp + (size_t)(row0 + 8) * Nout + col0) =
                    (uint32_t)__half_as_ushort(h2) | ((uint32_t)__half_as_ushort(h3) << 16);
                *(uint32_t*)(Cp + cPstride + (size_t)(row0 + 8) * Nout + col0) =
                    packh(o2 - __half2float(h2), o3 - __half2float(h3));
            }
            if (OUTMODE & 4) {
                *(uint32_t*)(Cp + (size_t)row0 * Nout + col0) = packh(o0, o1);
                *(uint32_t*)(Cp + (size_t)(row0 + 8) * Nout + col0) = packh(o2, o3);
            }
        }
    }
}

// ---------------- merged weight prep (single launch, region dispatch) ----------------
__global__ void prep_kernel(
    const float* __restrict__ W1, const float* __restrict__ Wa,
    const float* __restrict__ Wb, const float* __restrict__ W2,
    const float* __restrict__ Wc, const float* __restrict__ Wbil,
    const float* __restrict__ Wa1, const float* __restrict__ Wa2,
    __half* __restrict__ W1P, __half* __restrict__ WabP,
    __half* __restrict__ WfP, __half* __restrict__ WbTP,
    __half* __restrict__ Wa1P, __half* __restrict__ Wa2P)
{
    int i = blockIdx.x * 256 + threadIdx.x;
    float w;
    __half* out;
    int pstride, local;

    if (i < 262144) {
        local = i; w = W1[local]; out = W1P; pstride = 262144;
    } else if (i < 524288) {
        local = i - 262144;
        int nrow = local >> 8, k = local & 255;
        int j = nrow >> 6, r = nrow & 63;
        w = (r < 32) ? Wa[(j * 32 + r) * 256 + k] : Wb[(j * 32 + r - 32) * 256 + k];
        out = WabP; pstride = 262144;
    } else if (i < 655360) {
        local = i - 524288;
        int r = local >> 9, c = local & 511;
        float s = 0.0f;
        for (int k = 0; k < 256; k++) s += W2[r * 256 + k] * Wc[k * 512 + c];
        w = s; out = WfP; pstride = 131072;
    } else if (i < 720896) {
        local = i - 655360;
        int nrow = local >> 8, k = local & 255;
        w = Wbil[k * 256 + nrow];
        out = WbTP; pstride = 65536;
    } else if (i < 983040) {
        local = i - 720896; w = Wa1[local]; out = Wa1P; pstride = 262144;
    } else {
        local = i - 983040; w = Wa2[local]; out = Wa2P; pstride = 524288;
    }

    float r = w * WSCALE;
    __half h = __float2half(r);
    out[local] = h;
    r -= __half2float(h);
    out[(size_t)pstride + local] = __float2half(r);
}

// ---------------- elementwise ----------------
template <int NC>
__global__ void rmsnorm_kernel(float* __restrict__ x, const float* __restrict__ g, int rows)
{
    int row = blockIdx.x * 8 + (threadIdx.x >> 5);
    int lane = threadIdx.x & 31;
    if (row >= rows) return;
    float* p = x + (size_t)row * NC;
    constexpr int V = NC / 32;
    float v[V];
    float ss = 0.0f;
#pragma unroll
    for (int i = 0; i < V; i++) { v[i] = p[lane + 32 * i]; ss += v[i] * v[i]; }
#pragma unroll
    for (int o = 16; o > 0; o >>= 1) ss += __shfl_xor_sync(0xffffffffu, ss, o);
    float sc = rsqrtf(ss * (1.0f / NC) + 1e-6f);
#pragma unroll
    for (int i = 0; i < V; i++) p[lane + 32 * i] = v[i] * sc * g[lane + 32 * i];
}

__global__ void rmsnorm_planes(const float* __restrict__ x, const float* __restrict__ g,
                               __half* __restrict__ out, int rows)
{
    int row = blockIdx.x * 8 + (threadIdx.x >> 5);
    int lane = threadIdx.x & 31;
    if (row >= rows) return;
    const float* p = x + (size_t)row * 256;
    float v[8];
    float ss = 0.0f;
#pragma unroll
    for (int i = 0; i < 8; i++) { v[i] = p[lane + 32 * i]; ss += v[i] * v[i]; }
#pragma unroll
    for (int o = 16; o > 0; o >>= 1) ss += __shfl_xor_sync(0xffffffffu, ss, o);
    float sc = rsqrtf(ss * (1.0f / 256.0f) + 1e-6f);
#pragma unroll
    for (int i = 0; i < 8; i++) {
        float o = v[i] * sc * g[lane + 32 * i];
        __half h = __float2half(o);
        out[(size_t)row * 256 + lane + 32 * i] = h;
        out[PX1 + (size_t)row * 256 + lane + 32 * i] = __float2half(o - __half2float(h));
    }
}

// ---------------- per-batch sinkhorn etc ----------------
__global__ __launch_bounds__(256) void batch_kernel(
    const float* __restrict__ u, const float* __restrict__ tgt,
    const float* __restrict__ src, const float* __restrict__ bbil,
    const float* __restrict__ Wc1, const float* __restrict__ bc1,
    float* __restrict__ out_mapping, float* __restrict__ out_mapped,
    float* __restrict__ out_conf, __half* __restrict__ combP)
{
    const int b = blockIdx.x;
    const int tid = threadIdx.x;
    __shared__ float u_s[RROLE * HDIM];
    __shared__ float t_s[RROLE * HDIM];
    __shared__ float s_s[RROLE * HDIM];
    __shared__ float la[RROLE * RROLE];
    __shared__ float map_s[RROLE * RROLE];
    __shared__ float lse[RROLE];
    __shared__ float red[256];

    const size_t base = (size_t)b * RROLE * HDIM;
    for (int e = tid; e < RROLE * HDIM; e += 256) {
        u_s[e] = u[base + e];
        t_s[e] = tgt[base + e];
        s_s[e] = src[base + e];
    }
    __syncthreads();

    const float bb = bbil[0];
    const int warp = tid >> 5, lane = tid & 31;
    for (int p = warp; p < RROLE * RROLE; p += 8) {
        int i = p / RROLE, j = p % RROLE;
        float d = 0.0f;
        for (int h = lane; h < HDIM; h += 32) d += u_s[i * HDIM + h] * t_s[j * HDIM + h];
#pragma unroll
        for (int o = 16; o > 0; o >>= 1) d += __shfl_xor_sync(0xffffffffu, d, o);
        if (lane == 0) la[p] = (d + bb) * TEMP_INV;
    }
    __syncthreads();

    for (int it = 0; it < SINKHORN_ITERS; it++) {
        if (tid < RROLE) {
            float m = -1e30f;
            for (int j = 0; j < RROLE; j++) m = fmaxf(m, la[tid * RROLE + j]);
            float s = 0.0f;
            for (int j = 0; j < RROLE; j++) s += expf(la[tid * RROLE + j] - m);
            lse[tid] = m + logf(s);
        }
        __syncthreads();
        if (tid < RROLE * RROLE) la[tid] -= lse[tid / RROLE];
        __syncthreads();
        if (tid < RROLE) {
            float m = -1e30f;
            for (int i = 0; i < RROLE; i++) m = fmaxf(m, la[i * RROLE + tid]);
            float s = 0.0f;
            for (int i = 0; i < RROLE; i++) s += expf(la[i * RROLE + tid] - m);
            lse[tid] = m + logf(s);
        }
        __syncthreads();
        if (tid < RROLE * RROLE) la[tid] -= lse[tid % RROLE];
        __syncthreads();
    }

    if (tid < RROLE * RROLE) {
        float mv = expf(la[tid]);
        map_s[tid] = mv;
        out_mapping[(size_t)b * RROLE * RROLE + tid] = mv;
    }
    __syncthreads();

    float local = 0.0f;
    for (int e = tid; e < RROLE * HDIM; e += 256) {
        int i = e >> 8;
        int h = e & 255;
        float v = 0.0f;
#pragma unroll
        for (int j = 0; j < RROLE; j++) v += map_s[i * RROLE + j] * t_s[j * HDIM + h];
        out_mapped[base + e] = v;
        size_t cbase = ((size_t)b * RROLE + i) * 512;
        combP[cbase + h] = __float2half(v);
        combP[cbase + 256 + h] = __float2half(t_s[i * HDIM + h]);
        local += fabsf(v - s_s[e]);
    }
    red[tid] = local;
    __syncthreads();
    for (int s = 128; s > 0; s >>= 1) {
        if (tid < s) red[tid] += red[tid + s];
        __syncthreads();
    }
    if (tid == 0) {
        float conf_in = red[0] * (1.0f / (RROLE * HDIM));
        float z = conf_in * Wc1[0] + bc1[0];
        out_conf[b] = 1.0f / (1.0f + expf(-z));
    }
}

// ---------------- launch ----------------
#define SMEM3 61440
#define SMEM1 46080

extern "C" void kernel_launch(void* const* d_in, const int* in_sizes, int n_in,
                              void* d_out, int out_size)
{
    (void)in_sizes; (void)n_in; (void)out_size;
    const float* src  = (const float*)d_in[0];
    const float* tgt  = (const float*)d_in[1];
    const float* W1   = (const float*)d_in[2];
    const float* b1   = (const float*)d_in[3];
    const float* g1   = (const float*)d_in[4];
    const float* Wa   = (const float*)d_in[5];
    const float* Wb   = (const float*)d_in[6];
    const float* Wc   = (const float*)d_in[7];
    const float* W2   = (const float*)d_in[8];
    const float* b2   = (const float*)d_in[9];
    const float* Wbil = (const float*)d_in[10];
    const float* bbil = (const float*)d_in[11];
    const float* Wa1  = (const float*)d_in[12];
    const float* ba1  = (const float*)d_in[13];
    const float* Wa2  = (const float*)d_in[14];
    const float* ba2  = (const float*)d_in[15];
    const float* g2   = (const float*)d_in[16];
    const float* Wc1  = (const float*)d_in[17];
    const float* bc1  = (const float*)d_in[18];
    float* out = (float*)d_out;

    float *x1, *enc, *ub;
    __half *x1P, *hP, *encP, *combP, *bigP;
    __half *W1P, *WabP, *WfP, *WbTP, *Wa1P, *Wa2P;
    cudaGetSymbolAddress((void**)&x1,    g_x1);
    cudaGetSymbolAddress((void**)&enc,   g_enc);
    cudaGetSymbolAddress((void**)&ub,    g_u);
    cudaGetSymbolAddress((void**)&x1P,   g_x1P);
    cudaGetSymbolAddress((void**)&hP,    g_hP);
    cudaGetSymbolAddress((void**)&encP,  g_encP);
    cudaGetSymbolAddress((void**)&combP, g_combP);
    cudaGetSymbolAddress((void**)&bigP,  g_bigP);
    cudaGetSymbolAddress((void**)&W1P,   g_W1P);
    cudaGetSymbolAddress((void**)&WabP,  g_WabP);
    cudaGetSymbolAddress((void**)&WfP,   g_WfP);
    cudaGetSymbolAddress((void**)&WbTP,  g_WbTP);
    cudaGetSymbolAddress((void**)&Wa1P,  g_Wa1P);
    cudaGetSymbolAddress((void**)&Wa2P,  g_Wa2P);

    cudaFuncSetAttribute(gemm_l1, cudaFuncAttributeMaxDynamicSharedMemorySize, SMEM_L1);
    cudaFuncSetAttribute(gemm_mma<0,11,3>, cudaFuncAttributeMaxDynamicSharedMemorySize, SMEM3);
    cudaFuncSetAttribute(gemm_mma<0,1,3>, cudaFuncAttributeMaxDynamicSharedMemorySize, SMEM3);
    cudaFuncSetAttribute(gemm_mma<2,2,3>, cudaFuncAttributeMaxDynamicSharedMemorySize, SMEM3);
    cudaFuncSetAttribute(gemm_mma<1,4,1>, cudaFuncAttributeMaxDynamicSharedMemorySize, SMEM1);
    cudaFuncSetAttribute(gemm_mma<0,1,1>, cudaFuncAttributeMaxDynamicSharedMemorySize, SMEM1);

    // ---- merged weight prep (single launch; 1,507,328 elements) ----
    prep_kernel<<<5888, 256>>>(W1, Wa, Wb, W2, Wc, Wbil, Wa1, Wa2,
                               W1P, WabP, WfP, WbTP, Wa1P, Wa2P);

    // ---- merged encoder (src rows 0..M-1, tgt rows M..2M-1) ----
    gemm_l1<<<dim3(4, M2 / 128), 256, SMEM_L1>>>(
        src, tgt, W1P, 262144, b1, x1, 256, 1024, 256);
    rmsnorm_planes<<<M2 / 8, 256>>>(x1, g1, x1P, M2);
    gemm_mma<2,2,3><<<dim3(16, M2 / 128), 256, SMEM3>>>(
        x1P, PX1, WabP, 262144, nullptr, nullptr, hP, PH, 1024, 256, 512);
    gemm_mma<0,11,3><<<dim3(4, M2 / 128), 256, SMEM3>>>(
        hP, PH, WfP, 131072, b2, enc, encP, PE, 256, 512, 256);

    // ---- bilinear u = enc_src @ Wbil (first MROWS rows of encP) ----
    gemm_mma<0,1,3><<<dim3(4, MROWS / 128), 256, SMEM3>>>(
        encP, PE, WbTP, 65536, nullptr, ub, nullptr, 0, 256, 256, 256);

    // ---- sinkhorn / mapping / confidence / combined (hi plane only) ----
    batch_kernel<<<BATCH, 256>>>(ub, enc + (size_t)MROWS * 256, enc, bbil, Wc1, bc1,
                                 out + OUT_MAPPING_OFF, out + OUT_MAPPED_OFF,
                                 out + OUT_CONF_OFF, combP);

    // ---- answer projection (1-product path: hi x hi only, 3-stage, 4 CTAs/SM) ----
    gemm_mma<1,4,1><<<dim3(8, MROWS / 128), 256, SMEM1>>>(
        combP, 0, Wa1P, 262144, ba1, nullptr, bigP, 0, 512, 512, 512);
    gemm_mma<0,1,1><<<dim3(16, MROWS / 128), 256, SMEM1>>>(
        bigP, 0, Wa2P, 524288, ba2, out + OUT_ANSWER_OFF, nullptr, 0, 1024, 512, 1024);
    rmsnorm_kernel<DDIM><<<MROWS / 8, 256>>>(out + OUT_ANSWER_OFF, g2, MROWS);
}

// round 17
// speedup vs baseline: 1.1849x; 1.0825x over previous
#include <cuda_runtime.h>
#include <cuda_fp16.h>
#include <cstdint>
#include <math.h>

#define BATCH 8192
#define RROLE 6
#define DDIM 1024
#define HDIM 256
#define MROWS (BATCH * RROLE)          // 49152
#define M2 (2 * MROWS)                 // 98304 (src+tgt merged)
#define TEMP_INV 2.0f
#define SINKHORN_ITERS 5

#define OUT_ANSWER_OFF  0
#define OUT_MAPPING_OFF ((size_t)MROWS * DDIM)
#define OUT_MAPPED_OFF  (OUT_MAPPING_OFF + (size_t)BATCH * RROLE * RROLE)
#define OUT_CONF_OFF    (OUT_MAPPED_OFF + (size_t)MROWS * HDIM)

#define WSCALE 1024.0f
#define ISCALE (1.0f / 1024.0f)

// plane strides (elements per plane)
#define PX1  ((size_t)M2 * 256)
#define PH   ((size_t)M2 * 512)
#define PE   ((size_t)M2 * 256)

// ---------------- device scratch ----------------
__device__ float g_x1[(size_t)M2 * 256];
__device__ float g_enc[(size_t)M2 * 256];          // rows 0..M-1 src, M..2M-1 tgt
__device__ float g_u[(size_t)MROWS * 256];

__device__ __half g_x1P  [2 * (size_t)M2 * 256];
__device__ __half g_hP   [2 * (size_t)M2 * 512];
__device__ __half g_encP [2 * (size_t)M2 * 256];
__device__ __half g_combP[(size_t)MROWS * 512];    // hi plane only (answer path)
__device__ __half g_bigP [(size_t)MROWS * 512];    // hi plane only

// fp16 weight planes (2 planes each, scaled by WSCALE)
__device__ __half g_W1P [2 * 256 * 1024];
__device__ __half g_WabP[2 * 1024 * 256];   // interleaved gate/value rows
__device__ __half g_WfP [2 * 256 * 512];
__device__ __half g_WbTP[2 * 256 * 256];
__device__ __half g_Wa1P[2 * 512 * 512];
__device__ __half g_Wa2P[2 * 1024 * 512];

// ---------------- helpers ----------------
__device__ __forceinline__ uint32_t smem_u32(const void* p) {
    uint32_t a;
    asm("{ .reg .u64 t; cvta.to.shared.u64 t, %1; cvt.u32.u64 %0, t; }" : "=r"(a) : "l"(p));
    return a;
}
__device__ __forceinline__ float gelu_tanh(float x) {
    float x3 = x * x * x;
    return 0.5f * x * (1.0f + tanhf(0.7978845608028654f * (x + 0.044715f * x3)));
}
__device__ __forceinline__ void ldsm4(uint32_t& r0, uint32_t& r1, uint32_t& r2, uint32_t& r3,
                                      uint32_t addr) {
    asm volatile("ldmatrix.sync.aligned.m8n8.x4.shared.b16 {%0,%1,%2,%3}, [%4];"
                 : "=r"(r0), "=r"(r1), "=r"(r2), "=r"(r3) : "r"(addr));
}
__device__ __forceinline__ void mma16816(float* c, const uint32_t* a, const uint32_t* b) {
    asm volatile("mma.sync.aligned.m16n8k16.row.col.f32.f16.f16.f32 "
                 "{%0,%1,%2,%3}, {%4,%5,%6,%7}, {%8,%9}, {%0,%1,%2,%3};"
                 : "+f"(c[0]), "+f"(c[1]), "+f"(c[2]), "+f"(c[3])
                 : "r"(a[0]), "r"(a[1]), "r"(a[2]), "r"(a[3]), "r"(b[0]), "r"(b[1]));
}
__device__ __forceinline__ uint32_t packh(float x, float y) {
    __half h0 = __float2half(x), h1 = __float2half(y);
    return (uint32_t)__half_as_ushort(h0) | ((uint32_t)__half_as_ushort(h1) << 16);
}
#define CP_ASYNC16(dst, src) \
    asm volatile("cp.async.cg.shared.global [%0], [%1], 16;" :: "r"(dst), "l"(src) : "memory")
#define CP_COMMIT() asm volatile("cp.async.commit_group;" ::: "memory")
#define CP_WAIT0()  asm volatile("cp.async.wait_group 0;" ::: "memory")
#define CP_WAIT1()  asm volatile("cp.async.wait_group 1;" ::: "memory")
#define CP_WAIT2()  asm volatile("cp.async.wait_group 2;" ::: "memory")

// ---------------- layer1 GEMM: fp32 A, in-kernel split, 2-stage (padded layout) ----------------
#define GBUF 30720
#define SMEM_L1 61440

__global__ __launch_bounds__(256, 3) void gemm_l1(
    const float* __restrict__ Asrc, const float* __restrict__ Atgt,
    const __half* __restrict__ Bp, size_t bPstride,
    const float* __restrict__ bias, float* __restrict__ Cf,
    int N, int K, int Nout)
{
    extern __shared__ char smem[];
    const uint32_t sb = smem_u32(smem);
    const int tid = threadIdx.x, lane = tid & 31, wid = tid >> 5;
    const int bm = blockIdx.y * 128, bn = blockIdx.x * 64;
    const int wm = (wid >> 1) * 32, wn = (wid & 1) * 32;

    const float* A = (bm < MROWS) ? Asrc : (Atgt - (size_t)MROWS * K);

    const uint32_t aLd0 = sb + (uint32_t)((wm + (lane & 15)) * 80 + (lane >> 4) * 16);
    const uint32_t bLd0 = sb + 20480u +
        (uint32_t)(((wn + (lane & 7) + ((lane >> 4) & 1) * 8) * 80) + ((lane >> 3) & 1) * 16);

    float acc[2][4][4];
#pragma unroll
    for (int mt = 0; mt < 2; mt++)
#pragma unroll
        for (int nt = 0; nt < 4; nt++)
#pragma unroll
            for (int i = 0; i < 4; i++) acc[mt][nt][i] = 0.0f;

    const int nkb = K >> 5;

    const int arow = tid >> 1, acol = (tid & 1) * 16;
    const float* aBase = A + (size_t)(bm + arow) * K + acol;
    const uint32_t aStsOff = (uint32_t)(arow * 80 + acol * 2);
    const int brow = tid >> 2, bseg = tid & 3;
    const __half* bBase = Bp + (size_t)(bn + brow) * K + bseg * 8;
    const uint32_t bSts = sb + 20480u + (uint32_t)(brow * 80 + bseg * 16);

    {
        float v[16];
#pragma unroll
        for (int j = 0; j < 4; j++)
            *(float4*)(v + j * 4) = *(const float4*)(aBase + j * 4);
        uint32_t hp[8], lp[8];
#pragma unroll
        for (int j = 0; j < 8; j++) {
            __half h0 = __float2half(v[2 * j]), h1 = __float2half(v[2 * j + 1]);
            hp[j] = (uint32_t)__half_as_ushort(h0) | ((uint32_t)__half_as_ushort(h1) << 16);
            lp[j] = packh(v[2 * j] - __half2float(h0), v[2 * j + 1] - __half2float(h1));
        }
        *(uint4*)(smem + aStsOff)              = *(uint4*)hp;
        *(uint4*)(smem + aStsOff + 16)         = *(uint4*)(hp + 4);
        *(uint4*)(smem + aStsOff + 10240)      = *(uint4*)lp;
        *(uint4*)(smem + aStsOff + 10240 + 16) = *(uint4*)(lp + 4);
#pragma unroll
        for (int pl = 0; pl < 2; pl++)
            CP_ASYNC16(bSts + pl * 5120u, bBase + (size_t)pl * bPstride);
        CP_COMMIT();
        CP_WAIT0();
        __syncthreads();
    }

    for (int kb = 0; kb < nkb; kb++) {
        const uint32_t cur = (uint32_t)(kb & 1) * GBUF;
        const uint32_t nxt = (uint32_t)((kb + 1) & 1) * GBUF;
        const bool has = (kb + 1) < nkb;

        float vstage[16];
        if (has) {
            const float* ap = aBase + (kb + 1) * 32;
#pragma unroll
            for (int j = 0; j < 4; j++)
                *(float4*)(vstage + j * 4) = *(const float4*)(ap + j * 4);
            const __half* bp = bBase + (kb + 1) * 32;
#pragma unroll
            for (int pl = 0; pl < 2; pl++)
                CP_ASYNC16(bSts + nxt + pl * 5120u, bp + (size_t)pl * bPstride);
        }
        CP_COMMIT();

#pragma unroll
        for (int ks = 0; ks < 2; ks++) {
            uint32_t af[2][2][4];
#pragma unroll
            for (int mt = 0; mt < 2; mt++)
#pragma unroll
                for (int pl = 0; pl < 2; pl++)
                    ldsm4(af[mt][pl][0], af[mt][pl][1], af[mt][pl][2], af[mt][pl][3],
                          aLd0 + cur + pl * 10240u + mt * 16 * 80 + ks * 32);
            uint32_t bf[2][4][2];
#pragma unroll
            for (int pl = 0; pl < 2; pl++)
#pragma unroll
                for (int nt2 = 0; nt2 < 2; nt2++) {
                    uint32_t r0, r1, r2, r3;
                    ldsm4(r0, r1, r2, r3,
                          bLd0 + cur + pl * 5120u + nt2 * 16 * 80 + ks * 32);
                    bf[pl][nt2 * 2][0] = r0; bf[pl][nt2 * 2][1] = r1;
                    bf[pl][nt2 * 2 + 1][0] = r2; bf[pl][nt2 * 2 + 1][1] = r3;
                }
#pragma unroll
            for (int prod = 0; prod < 3; prod++) {
                const int apl = (prod == 2) ? 1 : 0;
                const int bpl = (prod == 1) ? 1 : 0;
#pragma unroll
                for (int mt = 0; mt < 2; mt++)
#pragma unroll
                    for (int nt = 0; nt < 4; nt++)
                        mma16816(acc[mt][nt], af[mt][apl], bf[bpl][nt]);
            }
        }

        if (has) {
            uint32_t hp[8], lp[8];
#pragma unroll
            for (int j = 0; j < 8; j++) {
                __half h0 = __float2half(vstage[2 * j]), h1 = __float2half(vstage[2 * j + 1]);
                hp[j] = (uint32_t)__half_as_ushort(h0) | ((uint32_t)__half_as_ushort(h1) << 16);
                lp[j] = packh(vstage[2 * j] - __half2float(h0), vstage[2 * j + 1] - __half2float(h1));
            }
            uint32_t off = aStsOff + nxt;
            *(uint4*)(smem + off)              = *(uint4*)hp;
            *(uint4*)(smem + off + 16)         = *(uint4*)(hp + 4);
            *(uint4*)(smem + off + 10240)      = *(uint4*)lp;
            *(uint4*)(smem + off + 10240 + 16) = *(uint4*)(lp + 4);
        }
        CP_WAIT0();
        __syncthreads();
    }

#pragma unroll
    for (int mt = 0; mt < 2; mt++) {
        int row0 = bm + wm + mt * 16 + (lane >> 2);
#pragma unroll
        for (int nt = 0; nt < 4; nt++) {
            int col0 = bn + wn + nt * 8 + (lane & 3) * 2;
            float b0 = bias[col0], b1 = bias[col0 + 1];
            *(float2*)(Cf + (size_t)row0 * Nout + col0) =
                make_float2(acc[mt][nt][0] * ISCALE + b0, acc[mt][nt][1] * ISCALE + b1);
            *(float2*)(Cf + (size_t)(row0 + 8) * Nout + col0) =
                make_float2(acc[mt][nt][2] * ISCALE + b0, acc[mt][nt][3] * ISCALE + b1);
        }
    }
}

// ---------------- HMMA GEMM (swizzled smem, deeper pipeline) ----------------
// Pitch-64 rows with chunk swizzle c ^= (row>>1)&3 (conflict-free stores + ldmatrix).
// NPROD=3: 3 stages, 3 CTAs/SM (73728 B). NPROD=1: 4 stages, 4 CTAs/SM (49152 B).
// ACT: 0 none, 1 gelu, 2 swiglu. OUTMODE bit0 fp32, bit1 fp16 hi+lo, bit2 fp16 hi,
// bit3: plane outputs only for rows < MROWS.
template <int ACT, int OUTMODE, int NPROD>
__global__ __launch_bounds__(256, (NPROD == 1) ? 4 : 3) void gemm_mma(
    const __half* __restrict__ Ap, size_t aPstride,
    const __half* __restrict__ Bp, size_t bPstride,
    const float* __restrict__ bias,
    float* __restrict__ Cf,
    __half* __restrict__ Cp, size_t cPstride,
    int N, int K, int Nout)
{
    constexpr int A_PL = (NPROD == 3) ? 2 : 1;
    constexpr int B_PL = (NPROD >= 2) ? 2 : 1;
    constexpr uint32_t ASZ = A_PL * 8192u;
    constexpr uint32_t STG_SZ = ASZ + B_PL * 4096u;
    constexpr int NSTG = (NPROD == 1) ? 4 : 3;

    extern __shared__ char smem[];
    const uint32_t sb = smem_u32(smem);
    const int tid = threadIdx.x, lane = tid & 31, wid = tid >> 5;
    const int bm = blockIdx.y * 128, bn = blockIdx.x * 64;
    const int wm = (wid >> 1) * 32, wn = (wid & 1) * 32;

    // lane-constant ldmatrix address pieces (swizzled)
    const uint32_t xrA = (uint32_t)(((lane & 15) >> 1) & 3);
    const uint32_t aRow = sb + (uint32_t)((wm + (lane & 15)) * 64);
    const uint32_t aHi = (uint32_t)(lane >> 4);                       // 0/1
    const uint32_t xrB = (uint32_t)(((lane & 7) >> 1) & 3);
    const uint32_t bRow = sb + ASZ +
        (uint32_t)((wn + (lane & 7) + ((lane >> 4) & 1) * 8) * 64);
    const uint32_t bHi = (uint32_t)((lane >> 3) & 1);                 // 0/1

    float acc[2][4][4];
#pragma unroll
    for (int mt = 0; mt < 2; mt++)
#pragma unroll
        for (int nt = 0; nt < 4; nt++)
#pragma unroll
            for (int i = 0; i < 4; i++) acc[mt][nt][i] = 0.0f;

    const int nkb = K >> 5;

    // rolling source pointers + fixed swizzled smem dst offsets
    const __half* aPtr[2 * A_PL];
    uint32_t aDst[2 * A_PL];
#pragma unroll
    for (int t = 0; t < 2 * A_PL; t++) {
        int idx = t * 256 + tid;
        int pl = idx >> 9, row = (idx >> 2) & 127, s = idx & 3;
        aPtr[t] = Ap + (size_t)pl * aPstride + (size_t)(bm + row) * K + s * 8;
        aDst[t] = (uint32_t)(pl * 8192 + row * 64 + ((s ^ ((row >> 1) & 3)) << 4));
    }
    const __half* bPtr[B_PL];
    uint32_t bDst[B_PL];
#pragma unroll
    for (int t = 0; t < B_PL; t++) {
        int idx = t * 256 + tid;
        int pl = idx >> 8, row = (idx >> 2) & 63, s = idx & 3;
        bPtr[t] = Bp + (size_t)pl * bPstride + (size_t)(bn + row) * K + s * 8;
        bDst[t] = ASZ + (uint32_t)(pl * 4096 + row * 64 + ((s ^ ((row >> 1) & 3)) << 4));
    }

    auto issue = [&](uint32_t base) {
#pragma unroll
        for (int t = 0; t < 2 * A_PL; t++) {
            CP_ASYNC16(sb + base + aDst[t], aPtr[t]);
            aPtr[t] += 32;
        }
#pragma unroll
        for (int t = 0; t < B_PL; t++) {
            CP_ASYNC16(sb + base + bDst[t], bPtr[t]);
            bPtr[t] += 32;
        }
    };

    issue(0);
    CP_COMMIT();
#pragma unroll
    for (int s = 1; s < NSTG - 1; s++) {
        if (nkb > s) issue(s * STG_SZ);
        CP_COMMIT();
    }

    uint32_t curStage = 0;
    for (int kb = 0; kb < nkb; kb++) {
        if (NSTG == 3) CP_WAIT1(); else CP_WAIT2();
        __syncthreads();
        const uint32_t cur = curStage * STG_SZ;
        uint32_t nxtStage = curStage + (NSTG - 1);
        if (nxtStage >= NSTG) nxtStage -= NSTG;
        if (kb + NSTG - 1 < nkb) issue(nxtStage * STG_SZ);
        CP_COMMIT();
        curStage = (curStage + 1 == NSTG) ? 0 : curStage + 1;

#pragma unroll
        for (int ks = 0; ks < 2; ks++) {
            const uint32_t caA = ((aHi + 2 * ks) ^ xrA) << 4;
            const uint32_t caB = ((bHi + 2 * ks) ^ xrB) << 4;
            uint32_t af[2][A_PL][4];
#pragma unroll
            for (int mt = 0; mt < 2; mt++)
#pragma unroll
                for (int pl = 0; pl < A_PL; pl++)
                    ldsm4(af[mt][pl][0], af[mt][pl][1], af[mt][pl][2], af[mt][pl][3],
                          aRow + cur + pl * 8192u + mt * 1024u + caA);
            uint32_t bf[B_PL][4][2];
#pragma unroll
            for (int pl = 0; pl < B_PL; pl++)
#pragma unroll
                for (int nt2 = 0; nt2 < 2; nt2++) {
                    uint32_t r0, r1, r2, r3;
                    ldsm4(r0, r1, r2, r3,
                          bRow + cur + pl * 4096u + nt2 * 1024u + caB);
                    bf[pl][nt2 * 2][0] = r0; bf[pl][nt2 * 2][1] = r1;
                    bf[pl][nt2 * 2 + 1][0] = r2; bf[pl][nt2 * 2 + 1][1] = r3;
                }
#pragma unroll
            for (int prod = 0; prod < NPROD; prod++) {
                const int apl = (prod == 2) ? 1 : 0;
                const int bpl = (prod == 1) ? 1 : 0;
#pragma unroll
                for (int mt = 0; mt < 2; mt++)
#pragma unroll
                    for (int nt = 0; nt < 4; nt++)
                        mma16816(acc[mt][nt], af[mt][apl], bf[bpl][nt]);
            }
        }
    }

    // ---- epilogue ----
    if (ACT == 2) {
        __syncthreads();
        float* vs = (float*)smem;
        if (wn == 32) {
#pragma unroll
            for (int mt = 0; mt < 2; mt++)
#pragma unroll
                for (int nt = 0; nt < 4; nt++) {
                    int r0 = wm + mt * 16 + (lane >> 2);
                    int c = nt * 8 + (lane & 3) * 2;
                    vs[r0 * 34 + c]           = acc[mt][nt][0] * ISCALE;
                    vs[r0 * 34 + c + 1]       = acc[mt][nt][1] * ISCALE;
                    vs[(r0 + 8) * 34 + c]     = acc[mt][nt][2] * ISCALE;
                    vs[(r0 + 8) * 34 + c + 1] = acc[mt][nt][3] * ISCALE;
                }
        }
        __syncthreads();
        if (wn == 0) {
#pragma unroll
            for (int mt = 0; mt < 2; mt++) {
                int r0 = wm + mt * 16 + (lane >> 2);
#pragma unroll
                for (int nt = 0; nt < 4; nt++) {
                    int c = nt * 8 + (lane & 3) * 2;
                    float g0 = acc[mt][nt][0] * ISCALE, g1 = acc[mt][nt][1] * ISCALE;
                    float g2 = acc[mt][nt][2] * ISCALE, g3 = acc[mt][nt][3] * ISCALE;
                    float o0 = g0 / (1.0f + expf(-g0)) * vs[r0 * 34 + c];
                    float o1 = g1 / (1.0f + expf(-g1)) * vs[r0 * 34 + c + 1];
                    float o2 = g2 / (1.0f + expf(-g2)) * vs[(r0 + 8) * 34 + c];
                    float o3 = g3 / (1.0f + expf(-g3)) * vs[(r0 + 8) * 34 + c + 1];
                    size_t row = (size_t)(bm + r0);
                    int col = (bn >> 1) + c;
                    __half h0 = __float2half(o0), h1 = __float2half(o1);
                    __half h2 = __float2half(o2), h3 = __float2half(o3);
                    *(uint32_t*)(Cp + row * Nout + col) =
                        (uint32_t)__half_as_ushort(h0) | ((uint32_t)__half_as_ushort(h1) << 16);
                    *(uint32_t*)(Cp + cPstride + row * Nout + col) =
                        packh(o0 - __half2float(h0), o1 - __half2float(h1));
                    *(uint32_t*)(Cp + (row + 8) * Nout + col) =
                        (uint32_t)__half_as_ushort(h2) | ((uint32_t)__half_as_ushort(h3) << 16);
                    *(uint32_t*)(Cp + cPstride + (row + 8) * Nout + col) =
                        packh(o2 - __half2float(h2), o3 - __half2float(h3));
                }
            }
        }
        return;
    }

    const bool doPlanes = !(OUTMODE & 8) || (bm < MROWS);

#pragma unroll
    for (int mt = 0; mt < 2; mt++) {
        int row0 = bm + wm + mt * 16 + (lane >> 2);
#pragma unroll
        for (int nt = 0; nt < 4; nt++) {
            int col0 = bn + wn + nt * 8 + (lane & 3) * 2;
            float b0 = 0.f, b1 = 0.f;
            if (bias) { b0 = bias[col0]; b1 = bias[col0 + 1]; }
            float o0 = acc[mt][nt][0] * ISCALE + b0;
            float o1 = acc[mt][nt][1] * ISCALE + b1;
            float o2 = acc[mt][nt][2] * ISCALE + b0;
            float o3 = acc[mt][nt][3] * ISCALE + b1;
            if (ACT == 1) {
                o0 = gelu_tanh(o0); o1 = gelu_tanh(o1);
                o2 = gelu_tanh(o2); o3 = gelu_tanh(o3);
            }
            if (OUTMODE & 1) {
                *(float2*)(Cf + (size_t)row0 * Nout + col0) = make_float2(o0, o1);
                *(float2*)(Cf + (size_t)(row0 + 8) * Nout + col0) = make_float2(o2, o3);
            }
            if ((OUTMODE & 2) && doPlanes) {
                __half h0 = __float2half(o0), h1 = __float2half(o1);
                __half h2 = __float2half(o2), h3 = __float2half(o3);
                *(uint32_t*)(Cp + (size_t)row0 * Nout + col0) =
                    (uint32_t)__half_as_ushort(h0) | ((uint32_t)__half_as_ushort(h1) << 16);
                *(uint32_t*)(Cp + cPstride + (size_t)row0 * Nout + col0) =
                    packh(o0 - __half2float(h0), o1 - __half2float(h1));
                *(uint32_t*)(Cp + (size_t)(row0 + 8) * Nout + col0) =
                    (uint32_t)__half_as_ushort(h2) | ((uint32_t)__half_as_ushort(h3) << 16);
                *(uint32_t*)(Cp + cPstride + (size_t)(row0 + 8) * Nout + col0) =
                    packh(o2 - __half2float(h2), o3 - __half2float(h3));
            }
            if (OUTMODE & 4) {
                *(uint32_t*)(Cp + (size_t)row0 * Nout + col0) = packh(o0, o1);
                *(uint32_t*)(Cp + (size_t)(row0 + 8) * Nout + col0) = packh(o2, o3);
            }
        }
    }
}

// ---------------- merged weight prep (single launch, region dispatch) ----------------
__global__ void prep_kernel(
    const float* __restrict__ W1, const float* __restrict__ Wa,
    const float* __restrict__ Wb, const float* __restrict__ W2,
    const float* __restrict__ Wc, const float* __restrict__ Wbil,
    const float* __restrict__ Wa1, const float* __restrict__ Wa2,
    __half* __restrict__ W1P, __half* __restrict__ WabP,
    __half* __restrict__ WfP, __half* __restrict__ WbTP,
    __half* __restrict__ Wa1P, __half* __restrict__ Wa2P)
{
    int i = blockIdx.x * 256 + threadIdx.x;
    float w;
    __half* out;
    int pstride, local;

    if (i < 262144) {
        local = i; w = W1[local]; out = W1P; pstride = 262144;
    } else if (i < 524288) {
        local = i - 262144;
        int nrow = local >> 8, k = local & 255;
        int j = nrow >> 6, r = nrow & 63;
        w = (r < 32) ? Wa[(j * 32 + r) * 256 + k] : Wb[(j * 32 + r - 32) * 256 + k];
        out = WabP; pstride = 262144;
    } else if (i < 655360) {
        local = i - 524288;
        int r = local >> 9, c = local & 511;
        float s = 0.0f;
        for (int k = 0; k < 256; k++) s += W2[r * 256 + k] * Wc[k * 512 + c];
        w = s; out = WfP; pstride = 131072;
    } else if (i < 720896) {
        local = i - 655360;
        int nrow = local >> 8, k = local & 255;
        w = Wbil[k * 256 + nrow];
        out = WbTP; pstride = 65536;
    } else if (i < 983040) {
        local = i - 720896; w = Wa1[local]; out = Wa1P; pstride = 262144;
    } else {
        local = i - 983040; w = Wa2[local]; out = Wa2P; pstride = 524288;
    }

    float r = w * WSCALE;
    __half h = __float2half(r);
    out[local] = h;
    r -= __half2float(h);
    out[(size_t)pstride + local] = __float2half(r);
}

// ---------------- elementwise ----------------
template <int NC>
__global__ void rmsnorm_kernel(float* __restrict__ x, const float* __restrict__ g, int rows)
{
    int row = blockIdx.x * 8 + (threadIdx.x >> 5);
    int lane = threadIdx.x & 31;
    if (row >= rows) return;
    float* p = x + (size_t)row * NC;
    constexpr int V = NC / 32;
    float v[V];
    float ss = 0.0f;
#pragma unroll
    for (int i = 0; i < V; i++) { v[i] = p[lane + 32 * i]; ss += v[i] * v[i]; }
#pragma unroll
    for (int o = 16; o > 0; o >>= 1) ss += __shfl_xor_sync(0xffffffffu, ss, o);
    float sc = rsqrtf(ss * (1.0f / NC) + 1e-6f);
#pragma unroll
    for (int i = 0; i < V; i++) p[lane + 32 * i] = v[i] * sc * g[lane + 32 * i];
}

__global__ void rmsnorm_planes(const float* __restrict__ x, const float* __restrict__ g,
                               __half* __restrict__ out, int rows)
{
    int row = blockIdx.x * 8 + (threadIdx.x >> 5);
    int lane = threadIdx.x & 31;
    if (row >= rows) return;
    const float* p = x + (size_t)row * 256;
    float v[8];
    float ss = 0.0f;
#pragma unroll
    for (int i = 0; i < 8; i++) { v[i] = p[lane + 32 * i]; ss += v[i] * v[i]; }
#pragma unroll
    for (int o = 16; o > 0; o >>= 1) ss += __shfl_xor_sync(0xffffffffu, ss, o);
    float sc = rsqrtf(ss * (1.0f / 256.0f) + 1e-6f);
#pragma unroll
    for (int i = 0; i < 8; i++) {
        float o = v[i] * sc * g[lane + 32 * i];
        __half h = __float2half(o);
        out[(size_t)row * 256 + lane + 32 * i] = h;
        out[PX1 + (size_t)row * 256 + lane + 32 * i] = __float2half(o - __half2float(h));
    }
}

// ---------------- per-batch sinkhorn etc ----------------
__global__ __launch_bounds__(256) void batch_kernel(
    const float* __restrict__ u, const float* __restrict__ tgt,
    const float* __restrict__ src, const float* __restrict__ bbil,
    const float* __restrict__ Wc1, const float* __restrict__ bc1,
    float* __restrict__ out_mapping, float* __restrict__ out_mapped,
    float* __restrict__ out_conf, __half* __restrict__ combP)
{
    const int b = blockIdx.x;
    const int tid = threadIdx.x;
    __shared__ float u_s[RROLE * HDIM];
    __shared__ float t_s[RROLE * HDIM];
    __shared__ float s_s[RROLE * HDIM];
    __shared__ float la[RROLE * RROLE];
    __shared__ float map_s[RROLE * RROLE];
    __shared__ float lse[RROLE];
    __shared__ float red[256];

    const size_t base = (size_t)b * RROLE * HDIM;
    for (int e = tid; e < RROLE * HDIM; e += 256) {
        u_s[e] = u[base + e];
        t_s[e] = tgt[base + e];
        s_s[e] = src[base + e];
    }
    __syncthreads();

    const float bb = bbil[0];
    const int warp = tid >> 5, lane = tid & 31;
    for (int p = warp; p < RROLE * RROLE; p += 8) {
        int i = p / RROLE, j = p % RROLE;
        float d = 0.0f;
        for (int h = lane; h < HDIM; h += 32) d += u_s[i * HDIM + h] * t_s[j * HDIM + h];
#pragma unroll
        for (int o = 16; o > 0; o >>= 1) d += __shfl_xor_sync(0xffffffffu, d, o);
        if (lane == 0) la[p] = (d + bb) * TEMP_INV;
    }
    __syncthreads();

    for (int it = 0; it < SINKHORN_ITERS; it++) {
        if (tid < RROLE) {
            float m = -1e30f;
            for (int j = 0; j < RROLE; j++) m = fmaxf(m, la[tid * RROLE + j]);
            float s = 0.0f;
            for (int j = 0; j < RROLE; j++) s += expf(la[tid * RROLE + j] - m);
            lse[tid] = m + logf(s);
        }
        __syncthreads();
        if (tid < RROLE * RROLE) la[tid] -= lse[tid / RROLE];
        __syncthreads();
        if (tid < RROLE) {
            float m = -1e30f;
            for (int i = 0; i < RROLE; i++) m = fmaxf(m, la[i * RROLE + tid]);
            float s = 0.0f;
            for (int i = 0; i < RROLE; i++) s += expf(la[i * RROLE + tid] - m);
            lse[tid] = m + logf(s);
        }
        __syncthreads();
        if (tid < RROLE * RROLE) la[tid] -= lse[tid % RROLE];
        __syncthreads();
    }

    if (tid < RROLE * RROLE) {
        float mv = expf(la[tid]);
        map_s[tid] = mv;
        out_mapping[(size_t)b * RROLE * RROLE + tid] = mv;
    }
    __syncthreads();

    float local = 0.0f;
    for (int e = tid; e < RROLE * HDIM; e += 256) {
        int i = e >> 8;
        int h = e & 255;
        float v = 0.0f;
#pragma unroll
        for (int j = 0; j < RROLE; j++) v += map_s[i * RROLE + j] * t_s[j * HDIM + h];
        out_mapped[base + e] = v;
        size_t cbase = ((size_t)b * RROLE + i) * 512;
        combP[cbase + h] = __float2half(v);
        combP[cbase + 256 + h] = __float2half(t_s[i * HDIM + h]);
        local += fabsf(v - s_s[e]);
    }
    red[tid] = local;
    __syncthreads();
    for (int s = 128; s > 0; s >>= 1) {
        if (tid < s) red[tid] += red[tid + s];
        __syncthreads();
    }
    if (tid == 0) {
        float conf_in = red[0] * (1.0f / (RROLE * HDIM));
        float z = conf_in * Wc1[0] + bc1[0];
        out_conf[b] = 1.0f / (1.0f + expf(-z));
    }
}

// ---------------- launch ----------------
#define SMEM3 73728
#define SMEM1 49152

extern "C" void kernel_launch(void* const* d_in, const int* in_sizes, int n_in,
                              void* d_out, int out_size)
{
    (void)in_sizes; (void)n_in; (void)out_size;
    const float* src  = (const float*)d_in[0];
    const float* tgt  = (const float*)d_in[1];
    const float* W1   = (const float*)d_in[2];
    const float* b1   = (const float*)d_in[3];
    const float* g1   = (const float*)d_in[4];
    const float* Wa   = (const float*)d_in[5];
    const float* Wb   = (const float*)d_in[6];
    const float* Wc   = (const float*)d_in[7];
    const float* W2   = (const float*)d_in[8];
    const float* b2   = (const float*)d_in[9];
    const float* Wbil = (const float*)d_in[10];
    const float* bbil = (const float*)d_in[11];
    const float* Wa1  = (const float*)d_in[12];
    const float* ba1  = (const float*)d_in[13];
    const float* Wa2  = (const float*)d_in[14];
    const float* ba2  = (const float*)d_in[15];
    const float* g2   = (const float*)d_in[16];
    const float* Wc1  = (const float*)d_in[17];
    const float* bc1  = (const float*)d_in[18];
    float* out = (float*)d_out;

    float *x1, *enc, *ub;
    __half *x1P, *hP, *encP, *combP, *bigP;
    __half *W1P, *WabP, *WfP, *WbTP, *Wa1P, *Wa2P;
    cudaGetSymbolAddress((void**)&x1,    g_x1);
    cudaGetSymbolAddress((void**)&enc,   g_enc);
    cudaGetSymbolAddress((void**)&ub,    g_u);
    cudaGetSymbolAddress((void**)&x1P,   g_x1P);
    cudaGetSymbolAddress((void**)&hP,    g_hP);
    cudaGetSymbolAddress((void**)&encP,  g_encP);
    cudaGetSymbolAddress((void**)&combP, g_combP);
    cudaGetSymbolAddress((void**)&bigP,  g_bigP);
    cudaGetSymbolAddress((void**)&W1P,   g_W1P);
    cudaGetSymbolAddress((void**)&WabP,  g_WabP);
    cudaGetSymbolAddress((void**)&WfP,   g_WfP);
    cudaGetSymbolAddress((void**)&WbTP,  g_WbTP);
    cudaGetSymbolAddress((void**)&Wa1P,  g_Wa1P);
    cudaGetSymbolAddress((void**)&Wa2P,  g_Wa2P);

    cudaFuncSetAttribute(gemm_l1, cudaFuncAttributeMaxDynamicSharedMemorySize, SMEM_L1);
    cudaFuncSetAttribute(gemm_mma<0,11,3>, cudaFuncAttributeMaxDynamicSharedMemorySize, SMEM3);
    cudaFuncSetAttribute(gemm_mma<0,1,3>, cudaFuncAttributeMaxDynamicSharedMemorySize, SMEM3);
    cudaFuncSetAttribute(gemm_mma<2,2,3>, cudaFuncAttributeMaxDynamicSharedMemorySize, SMEM3);
    cudaFuncSetAttribute(gemm_mma<1,4,1>, cudaFuncAttributeMaxDynamicSharedMemorySize, SMEM1);
    cudaFuncSetAttribute(gemm_mma<0,1,1>, cudaFuncAttributeMaxDynamicSharedMemorySize, SMEM1);

    // ---- merged weight prep (single launch; 1,507,328 elements) ----
    prep_kernel<<<5888, 256>>>(W1, Wa, Wb, W2, Wc, Wbil, Wa1, Wa2,
                               W1P, WabP, WfP, WbTP, Wa1P, Wa2P);

    // ---- merged encoder (src rows 0..M-1, tgt rows M..2M-1) ----
    gemm_l1<<<dim3(4, M2 / 128), 256, SMEM_L1>>>(
        src, tgt, W1P, 262144, b1, x1, 256, 1024, 256);
    rmsnorm_planes<<<M2 / 8, 256>>>(x1, g1, x1P, M2);
    gemm_mma<2,2,3><<<dim3(16, M2 / 128), 256, SMEM3>>>(
        x1P, PX1, WabP, 262144, nullptr, nullptr, hP, PH, 1024, 256, 512);
    gemm_mma<0,11,3><<<dim3(4, M2 / 128), 256, SMEM3>>>(
        hP, PH, WfP, 131072, b2, enc, encP, PE, 256, 512, 256);

    // ---- bilinear u = enc_src @ Wbil (first MROWS rows of encP) ----
    gemm_mma<0,1,3><<<dim3(4, MROWS / 128), 256, SMEM3>>>(
        encP, PE, WbTP, 65536, nullptr, ub, nullptr, 0, 256, 256, 256);

    // ---- sinkhorn / mapping / confidence / combined (hi plane only) ----
    batch_kernel<<<BATCH, 256>>>(ub, enc + (size_t)MROWS * 256, enc, bbil, Wc1, bc1,
                                 out + OUT_MAPPING_OFF, out + OUT_MAPPED_OFF,
                                 out + OUT_CONF_OFF, combP);

    // ---- answer projection (1-product path, 4-stage, 4 CTAs/SM) ----
    gemm_mma<1,4,1><<<dim3(8, MROWS / 128), 256, SMEM1>>>(
        combP, 0, Wa1P, 262144, ba1, nullptr, bigP, 0, 512, 512, 512);
    gemm_mma<0,1,1><<<dim3(16, MROWS / 128), 256, SMEM1>>>(
        bigP, 0, Wa2P, 524288, ba2, out + OUT_ANSWER_OFF, nullptr, 0, 1024, 512, 1024);
    rmsnorm_kernel<DDIM><<<MROWS / 8, 256>>>(out + OUT_ANSWER_OFF, g2, MROWS);
}